// round 1
// baseline (speedup 1.0000x reference)
#include <cuda_runtime.h>
#include <math.h>
#include <stdint.h>

// ---------------- static problem config ----------------
#define BB 32
#define TT 12
#define NNODE 500
#define FINC 2
#define UU 32
#define NDm 32
#define NRESC 32
#define NDILC 32
#define NSKIPC 256
#define NENDC 512
#define NPREDC 12
#define LL 8
#define RFh 13
#define BN_EPS 1e-5f

// ---------------- device scratch (no allocations allowed) ----------------
__device__ float g_v[NNODE * 32];
__device__ float g_P[NNODE * 64];
__device__ float g_Q[NNODE * 64];
__device__ float g_eraw[2 * NNODE * NNODE];
__device__ float g_Scat[NNODE * 2000];            // [v][ A0 | A0^2 | A1 | A1^2 ]
__device__ float g_tmp[BB * TT * 32 * 2];
__device__ float g_X0[BB * 32 * RFh * NNODE];
__device__ float g_X1[BB * 32 * RFh * NNODE];
__device__ float g_XG[BB * 32 * 12 * NNODE];
__device__ float g_Y[12288 * 2000];               // diffusion outputs; reused as head hidden H
__device__ float g_skip[BB * NSKIPC * NNODE];
__device__ float g_Srelu[BB * NNODE * NSKIPC];
__device__ float g_o1wT[NSKIPC * NENDC];
__device__ double g_stats[LL * 64];

// ---------------- tiny kernels ----------------
__global__ void k_zero_stats(double* st) {
    int t = threadIdx.x;
    if (t < LL * 64) st[t] = 0.0;
}

// v = relu(factor @ map_w + map_b)   [500,32]
__global__ void k_v(const float* __restrict__ factor, const float* __restrict__ map_w,
                    const float* __restrict__ map_b) {
    __shared__ float f[32];
    int n = blockIdx.x, d = threadIdx.x;
    f[d] = factor[n * 32 + d];
    __syncthreads();
    float acc = map_b[d];
#pragma unroll
    for (int u = 0; u < 32; u++) acc += f[u] * map_w[u * 32 + d];
    g_v[n * 32 + d] = fmaxf(acc, 0.f);
}

// P[j][h] = sum_d v[j][d]*a1w[d][h] ; Q[i][h] = a1b[h] + sum_d v[i][d]*a1w[32+d][h]
__global__ void k_pq(const float* __restrict__ a1w, const float* __restrict__ a1b) {
    __shared__ float vv[32];
    int j = blockIdx.x, h = threadIdx.x;
    if (h < 32) vv[h] = g_v[j * 32 + h];
    __syncthreads();
    float p = 0.f, q = a1b[h];
#pragma unroll
    for (int d = 0; d < 32; d++) {
        p += vv[d] * a1w[d * 64 + h];
        q += vv[d] * a1w[(32 + d) * 64 + h];
    }
    g_P[j * 64 + h] = p;
    g_Q[j * 64 + h] = q;
}

// per-pair MLP tail: h1=relu(P[j]+Q[i]) ; h2=relu(h1@a2w+b) ; e = h2@a3w+b
__global__ void k_adjmlp(const float* __restrict__ a2w, const float* __restrict__ a2b,
                         const float* __restrict__ a3w, const float* __restrict__ a3b) {
    __shared__ float Pt[128][65];
    __shared__ float sA2[64][32];
    __shared__ float sQ[64];
    __shared__ float sA3[64];
    __shared__ float sA2b[32];
    __shared__ float sA3b[2];
    int i = blockIdx.x, tid = threadIdx.x;
    for (int k = tid; k < 64 * 32; k += 128) sA2[k / 32][k % 32] = a2w[k];
    if (tid < 64) { sQ[tid] = g_Q[i * 64 + tid]; sA3[tid] = a3w[tid]; }
    if (tid < 32) sA2b[tid] = a2b[tid];
    if (tid < 2) sA3b[tid] = a3b[tid];
    for (int j0 = 0; j0 < NNODE; j0 += 128) {
        __syncthreads();
        int cnt = min(128, NNODE - j0);
        for (int k = tid; k < cnt * 64; k += 128)
            Pt[k / 64][k % 64] = g_P[(j0 + (k / 64)) * 64 + (k % 64)];
        __syncthreads();
        if (tid < cnt) {
            int j = j0 + tid;
            float h1[64];
#pragma unroll
            for (int h = 0; h < 64; h++) h1[h] = fmaxf(Pt[tid][h] + sQ[h], 0.f);
            float e0 = sA3b[0], e1 = sA3b[1];
#pragma unroll
            for (int c = 0; c < 32; c++) {
                float acc = sA2b[c];
#pragma unroll
                for (int h = 0; h < 64; h++) acc += h1[h] * sA2[h][c];
                acc = fmaxf(acc, 0.f);
                e0 += acc * sA3[c * 2];
                e1 += acc * sA3[c * 2 + 1];
            }
            g_eraw[i * NNODE + j] = e0;
            g_eraw[NNODE * NNODE + i * NNODE + j] = e1;
        }
    }
}

// softmax over j then max with eye; writes Scat columns and (optionally) d_out
__global__ void k_softmax(float* __restrict__ outSup, int writeSup) {
    int bid = blockIdx.x;           // 0..999
    int e = bid / NNODE, i = bid % NNODE;
    const float* row = g_eraw + e * NNODE * NNODE + i * NNODE;
    __shared__ float red[256];
    int tid = threadIdx.x;
    float m = -1e30f;
    for (int j = tid; j < NNODE; j += 256) m = fmaxf(m, row[j]);
    red[tid] = m; __syncthreads();
    for (int s = 128; s > 0; s >>= 1) { if (tid < s) red[tid] = fmaxf(red[tid], red[tid + s]); __syncthreads(); }
    m = red[0]; __syncthreads();
    float sum = 0.f;
    for (int j = tid; j < NNODE; j += 256) sum += expf(row[j] - m);
    red[tid] = sum; __syncthreads();
    for (int s = 128; s > 0; s >>= 1) { if (tid < s) red[tid] += red[tid + s]; __syncthreads(); }
    float inv = 1.f / red[0];
    for (int j = tid; j < NNODE; j += 256) {
        float p = expf(row[j] - m) * inv;
        if (j == i) p = fmaxf(p, 1.f);
        g_Scat[i * 2000 + e * 1000 + j] = p;
        if (writeSup) outSup[(e * NNODE + i) * NNODE + j] = p;
    }
}

// tmp[b,t,u,f] = sum_n inputs[b,t,n,f]*factor[n,u]
__global__ void k_tmp(const float* __restrict__ inputs, const float* __restrict__ factor) {
    int t = blockIdx.x, b = blockIdx.y, tid = threadIdx.x;
    int u = tid / 2, f = tid % 2;
    const float* inp = inputs + ((size_t)(b * TT + t) * NNODE) * 2 + f;
    float acc = 0.f;
    for (int n = 0; n < NNODE; n++) acc += inp[n * 2] * factor[n * 32 + u];
    g_tmp[(b * TT + t) * 64 + tid] = acc;
}

// static split + left pad + enter 1x1 conv -> X0 [B,32,13,N]
__global__ void k_enter(const float* __restrict__ inputs, const float* __restrict__ factor,
                        const float* __restrict__ ew, const float* __restrict__ eb,
                        float* __restrict__ X0) {
    __shared__ float sw[128], sb[32], stmp[64];
    int b = blockIdx.z, tp = blockIdx.y;
    int tid = threadIdx.x;
    if (tid < 128) sw[tid] = ew[tid];
    if (tid < 32) sb[tid] = eb[tid];
    if (tp > 0 && tid < 64) stmp[tid] = g_tmp[(b * TT + (tp - 1)) * 64 + tid];
    __syncthreads();
    int n = blockIdx.x * 128 + tid;
    if (n >= NNODE) return;
    if (tp == 0) {
#pragma unroll
        for (int o = 0; o < 32; o++)
            X0[((size_t)(b * 32 + o) * RFh + 0) * NNODE + n] = sb[o];
    } else {
        int t = tp - 1;
        float s0 = 0.f, s1 = 0.f;
#pragma unroll
        for (int u = 0; u < 32; u++) {
            float fv = factor[n * 32 + u];
            s0 += fv * stmp[u * 2];
            s1 += fv * stmp[u * 2 + 1];
        }
        float i0 = inputs[((size_t)(b * TT + t) * NNODE + n) * 2 + 0];
        float i1 = inputs[((size_t)(b * TT + t) * NNODE + n) * 2 + 1];
        float r0 = i0 - s0, r1 = i1 - s1;
#pragma unroll
        for (int o = 0; o < 32; o++) {
            float v = sb[o] + sw[o * 4] * s0 + sw[o * 4 + 1] * s1 + sw[o * 4 + 2] * r0 + sw[o * 4 + 3] * r1;
            X0[((size_t)(b * 32 + o) * RFh + tp) * NNODE + n] = v;
        }
    }
}

// gated dilated temporal conv: XG = tanh(filt)*sigmoid(gate)
__global__ void k_gatefilter(const float* __restrict__ X, float* __restrict__ XG,
                             const float* __restrict__ fw, const float* __restrict__ fb,
                             const float* __restrict__ gw, const float* __restrict__ gb,
                             int Tin, int Tout, int dd) {
    __shared__ float swf[2048], swg[2048], sfb[32], sgb[32];
    int tid = threadIdx.x;
    for (int idx = tid; idx < 2048; idx += 128) {
        int c = idx >> 6, r = idx & 63, o = r >> 1, kk = r & 1;
        swf[idx] = fw[(o << 6) + (c << 1) + kk];
        swg[idx] = gw[(o << 6) + (c << 1) + kk];
    }
    if (tid < 32) { sfb[tid] = fb[tid]; sgb[tid] = gb[tid]; }
    __syncthreads();
    int n = blockIdx.x * 128 + tid;
    if (n >= NNODE) return;
    int t = blockIdx.y, b = blockIdx.z;
    float fa[32], ga[32];
#pragma unroll
    for (int o = 0; o < 32; o++) { fa[o] = sfb[o]; ga[o] = sgb[o]; }
    const float* Xb = X + (size_t)(b * 32) * Tin * NNODE + n;
    for (int c = 0; c < 32; c++) {
        float xa = Xb[(size_t)(c * Tin + t) * NNODE];
        float xb = Xb[(size_t)(c * Tin + t + dd) * NNODE];
        const float4* wf4 = (const float4*)&swf[c * 64];
        const float4* wg4 = (const float4*)&swg[c * 64];
#pragma unroll
        for (int o2 = 0; o2 < 16; o2++) {
            float4 wf = wf4[o2];
            fa[o2 * 2 + 0] += wf.x * xa + wf.y * xb;
            fa[o2 * 2 + 1] += wf.z * xa + wf.w * xb;
            float4 wg = wg4[o2];
            ga[o2 * 2 + 0] += wg.x * xa + wg.y * xb;
            ga[o2 * 2 + 1] += wg.z * xa + wg.w * xb;
        }
    }
#pragma unroll
    for (int o = 0; o < 32; o++) {
        float s = 1.f / (1.f + expf(-ga[o]));
        XG[((size_t)(b * 32 + o) * Tout + t) * NNODE + n] = tanhf(fa[o]) * s;
    }
}

// skip accumulation — only the last time step of each layer matters
__global__ void k_skip(const float* __restrict__ XG, float* __restrict__ skip,
                       const float* __restrict__ sw_g, const float* __restrict__ sb_g,
                       int Tout, int first) {
    __shared__ float xs[8][32];
    int b = blockIdx.y;
    int n0 = blockIdx.x * 8;
    int tid = threadIdx.x;
    {
        int nn = tid / 32, c = tid % 32;
        int n = n0 + nn;
        xs[nn][c] = (n < NNODE) ? XG[((size_t)(b * 32 + c) * Tout + (Tout - 1)) * NNODE + n] : 0.f;
    }
    __syncthreads();
    int o = tid;
    float w[32];
#pragma unroll
    for (int c = 0; c < 32; c++) w[c] = sw_g[o * 32 + c];
    float bias = sb_g[o];
#pragma unroll
    for (int nn = 0; nn < 8; nn++) {
        int n = n0 + nn;
        if (n >= NNODE) break;
        float acc = bias;
#pragma unroll
        for (int c = 0; c < 32; c++) acc += w[c] * xs[nn][c];
        size_t idx = (size_t)(b * NSKIPC + o) * NNODE + n;
        if (first) skip[idx] = acc;
        else skip[idx] += acc;
    }
}

// generic fp32 GEMM: C[M,N] = A[M,K] @ B[K,N], row-major with leading dims
__global__ void gemm_kernel(const float* __restrict__ A, const float* __restrict__ B,
                            float* __restrict__ C, int M, int N, int K,
                            int lda, int ldb, int ldc) {
    __shared__ float As[64][17];
    __shared__ float Bs[16][64];
    int tid = threadIdx.x;
    int n0 = blockIdx.x * 64, m0 = blockIdx.y * 64;
    int tx = tid % 16, ty = tid / 16;
    int ak = tid % 16, am = tid / 16;
    int bn = tid % 64, bk = tid / 64;
    float acc[4][4];
#pragma unroll
    for (int i = 0; i < 4; i++)
#pragma unroll
        for (int j = 0; j < 4; j++) acc[i][j] = 0.f;
    for (int k0 = 0; k0 < K; k0 += 16) {
#pragma unroll
        for (int r = 0; r < 4; r++) {
            int mm = am + r * 16;
            int row = m0 + mm, col = k0 + ak;
            As[mm][ak] = (row < M && col < K) ? A[(size_t)row * lda + col] : 0.f;
        }
#pragma unroll
        for (int r = 0; r < 4; r++) {
            int kk = bk + r * 4;
            int row = k0 + kk, col = n0 + bn;
            Bs[kk][bn] = (row < K && col < N) ? B[(size_t)row * ldb + col] : 0.f;
        }
        __syncthreads();
#pragma unroll
        for (int kk = 0; kk < 16; kk++) {
            float a0 = As[ty * 4 + 0][kk];
            float a1 = As[ty * 4 + 1][kk];
            float a2 = As[ty * 4 + 2][kk];
            float a3 = As[ty * 4 + 3][kk];
            float4 b4 = *(const float4*)&Bs[kk][tx * 4];
            acc[0][0] += a0 * b4.x; acc[0][1] += a0 * b4.y; acc[0][2] += a0 * b4.z; acc[0][3] += a0 * b4.w;
            acc[1][0] += a1 * b4.x; acc[1][1] += a1 * b4.y; acc[1][2] += a1 * b4.z; acc[1][3] += a1 * b4.w;
            acc[2][0] += a2 * b4.x; acc[2][1] += a2 * b4.y; acc[2][2] += a2 * b4.z; acc[2][3] += a2 * b4.w;
            acc[3][0] += a3 * b4.x; acc[3][1] += a3 * b4.y; acc[3][2] += a3 * b4.z; acc[3][3] += a3 * b4.w;
        }
        __syncthreads();
    }
#pragma unroll
    for (int i = 0; i < 4; i++) {
        int row = m0 + ty * 4 + i;
        if (row >= M) continue;
#pragma unroll
        for (int j = 0; j < 4; j++) {
            int col = n0 + tx * 4 + j;
            if (col < N) C[(size_t)row * ldc + col] = acc[i][j];
        }
    }
}

// gc 1x1 over concat(x, xA0, xA0^2, xA1, xA1^2) + residual + BN stats (atomics)
__global__ void k_gcres(const float* __restrict__ XG, const float* __restrict__ Y,
                        const float* __restrict__ Xc, float* __restrict__ Xn,
                        const float* __restrict__ gcw, const float* __restrict__ gcb,
                        double* __restrict__ stats, int Tin, int Tout, int dd) {
    __shared__ float swg[160 * 32];
    __shared__ float sgb[32];
    __shared__ float sredS[4][32];
    __shared__ float sredQ[4][32];
    int tid = threadIdx.x;
    for (int idx = tid; idx < 160 * 32; idx += 128) {
        int c = idx / 32, o = idx % 32;
        swg[idx] = gcw[o * 160 + c];
    }
    if (tid < 32) sgb[tid] = gcb[tid];
    __syncthreads();
    int n = blockIdx.x * 128 + tid;
    int t = blockIdx.y, b = blockIdx.z;
    bool active = (n < NNODE);
    float acc[32];
#pragma unroll
    for (int o = 0; o < 32; o++) acc[o] = active ? sgb[o] : 0.f;
    if (active) {
        // block 0: x itself
        for (int c = 0; c < 32; c++) {
            float val = XG[((size_t)(b * 32 + c) * Tout + t) * NNODE + n];
            const float4* w4 = (const float4*)&swg[c * 32];
#pragma unroll
            for (int q = 0; q < 8; q++) {
                float4 w = w4[q];
                acc[q * 4 + 0] += w.x * val; acc[q * 4 + 1] += w.y * val;
                acc[q * 4 + 2] += w.z * val; acc[q * 4 + 3] += w.w * val;
            }
        }
        // blocks 1..4: diffusion outputs
        for (int e = 0; e < 4; e++) {
            for (int c = 0; c < 32; c++) {
                size_t m = (size_t)(b * 32 + c) * Tout + t;
                float val = Y[m * 2000 + e * 500 + n];
                const float4* w4 = (const float4*)&swg[(32 + e * 32 + c) * 32];
#pragma unroll
                for (int q = 0; q < 8; q++) {
                    float4 w = w4[q];
                    acc[q * 4 + 0] += w.x * val; acc[q * 4 + 1] += w.y * val;
                    acc[q * 4 + 2] += w.z * val; acc[q * 4 + 3] += w.w * val;
                }
            }
        }
#pragma unroll
        for (int o = 0; o < 32; o++) {
            acc[o] += Xc[((size_t)(b * 32 + o) * Tin + t + dd) * NNODE + n];
            Xn[((size_t)(b * 32 + o) * Tout + t) * NNODE + n] = acc[o];
        }
    }
    // BN statistics
    int lane = tid & 31, warp = tid >> 5;
#pragma unroll
    for (int o = 0; o < 32; o++) {
        float s = active ? acc[o] : 0.f;
        float q = s * s;
#pragma unroll
        for (int off = 16; off; off >>= 1) {
            s += __shfl_down_sync(0xffffffffu, s, off);
            q += __shfl_down_sync(0xffffffffu, q, off);
        }
        if (lane == 0) { sredS[warp][o] = s; sredQ[warp][o] = q; }
    }
    __syncthreads();
    if (tid < 64) {
        int o = tid & 31;
        bool isq = (tid >= 32);
        double v = 0.0;
#pragma unroll
        for (int w = 0; w < 4; w++) v += (double)(isq ? sredQ[w][o] : sredS[w][o]);
        atomicAdd(&stats[(isq ? 32 : 0) + o], v);
    }
}

__global__ void k_bnnorm(float* __restrict__ X, const double* __restrict__ stats,
                         const float* __restrict__ gg, const float* __restrict__ bta, int Tout) {
    int idx = blockIdx.x * 256 + threadIdx.x;
    int total = BB * 32 * Tout * NNODE;
    if (idx >= total) return;
    int c = (idx / (Tout * NNODE)) % 32;
    float cnt = (float)(BB * Tout * NNODE);
    float mean = (float)(stats[c]) / cnt;
    float var = (float)(stats[32 + c]) / cnt - mean * mean;
    float sc = gg[c] * rsqrtf(var + BN_EPS);
    X[idx] = (X[idx] - mean) * sc + bta[c];
}

// relu + transpose skip [B,256,N] -> Srelu [(b*N+n), 256]
__global__ void k_transpose_skip(const float* __restrict__ skip, float* __restrict__ Srelu) {
    __shared__ float tile[32][33];
    int b = blockIdx.z;
    int n0 = blockIdx.x * 32, c0 = blockIdx.y * 32;
    int n = n0 + threadIdx.x, c = c0 + threadIdx.y;
    tile[threadIdx.y][threadIdx.x] = (n < NNODE) ? skip[(size_t)(b * NSKIPC + c) * NNODE + n] : 0.f;
    __syncthreads();
    int n2 = n0 + threadIdx.y, c2 = c0 + threadIdx.x;
    if (n2 < NNODE)
        Srelu[(size_t)(b * NNODE + n2) * NSKIPC + c2] = fmaxf(tile[threadIdx.x][threadIdx.y], 0.f);
}

__global__ void k_transpose_o1w(const float* __restrict__ o1w, float* __restrict__ o1wT) {
    int idx = blockIdx.x * 256 + threadIdx.x;
    if (idx >= NENDC * NSKIPC) return;
    int h = idx / NSKIPC, c = idx % NSKIPC;
    o1wT[c * NENDC + h] = o1w[idx];
}

// final: y[b,p,n] = o2b[p] + sum_h o2w[p,h]*relu(H[row,h]+o1b[h])
__global__ void k_headfinal(const float* __restrict__ H, const float* __restrict__ o1b,
                            const float* __restrict__ o2w, const float* __restrict__ o2b,
                            float* __restrict__ out) {
    __shared__ float sh[512];
    int row = blockIdx.x;
    int b = row / NNODE, n = row % NNODE;
    int tid = threadIdx.x;
    for (int h = tid; h < 512; h += 128)
        sh[h] = fmaxf(H[(size_t)row * 512 + h] + o1b[h], 0.f);
    __syncthreads();
    if (tid < NPREDC) {
        float acc = o2b[tid];
#pragma unroll 8
        for (int h = 0; h < 512; h++) acc += o2w[tid * 512 + h] * sh[h];
        out[(size_t)(b * NPREDC + tid) * NNODE + n] = acc;
    }
}

// ---------------- host launcher ----------------
extern "C" void kernel_launch(void* const* d_in, const int* in_sizes, int n_in,
                              void* d_out, int out_size) {
    const float* inputs = (const float*)d_in[0];
    const float* factor = (const float*)d_in[1];
    const float* map_w  = (const float*)d_in[2];
    const float* map_b  = (const float*)d_in[3];
    const float* a1w    = (const float*)d_in[4];
    const float* a1b    = (const float*)d_in[5];
    const float* a2w    = (const float*)d_in[6];
    const float* a2b    = (const float*)d_in[7];
    const float* a3w    = (const float*)d_in[8];
    const float* a3b    = (const float*)d_in[9];
    const float* enter_w = (const float*)d_in[10];
    const float* enter_b = (const float*)d_in[11];
    const float* filt_w = (const float*)d_in[12];
    const float* filt_b = (const float*)d_in[13];
    const float* gate_w = (const float*)d_in[14];
    const float* gate_b = (const float*)d_in[15];
    const float* skp_w  = (const float*)d_in[16];
    const float* skp_b  = (const float*)d_in[17];
    const float* gc_w   = (const float*)d_in[18];
    const float* gc_b   = (const float*)d_in[19];
    const float* bn_g   = (const float*)d_in[20];
    const float* bn_b   = (const float*)d_in[21];
    const float* o1w    = (const float*)d_in[22];
    const float* o1b    = (const float*)d_in[23];
    const float* o2w    = (const float*)d_in[24];
    const float* o2b    = (const float*)d_in[25];

    float *pScat, *pY, *pX0, *pX1, *pXG, *pSkip, *pSrelu, *pO1T;
    double* pStats;
    cudaGetSymbolAddress((void**)&pScat, g_Scat);
    cudaGetSymbolAddress((void**)&pY, g_Y);
    cudaGetSymbolAddress((void**)&pX0, g_X0);
    cudaGetSymbolAddress((void**)&pX1, g_X1);
    cudaGetSymbolAddress((void**)&pXG, g_XG);
    cudaGetSymbolAddress((void**)&pSkip, g_skip);
    cudaGetSymbolAddress((void**)&pSrelu, g_Srelu);
    cudaGetSymbolAddress((void**)&pO1T, g_o1wT);
    cudaGetSymbolAddress((void**)&pStats, g_stats);

    float* out = (float*)d_out;
    const int ySize = BB * NPREDC * NNODE;           // 192000
    const int supSize = 2 * NNODE * NNODE;           // 500000
    int writeSup = (out_size >= ySize + supSize) ? 1 : 0;
    float* outSup = out + ySize;

    k_zero_stats<<<1, 512>>>(pStats);
    // adaptive adjacency
    k_v<<<NNODE, 32>>>(factor, map_w, map_b);
    k_pq<<<NNODE, 64>>>(a1w, a1b);
    k_adjmlp<<<NNODE, 128>>>(a2w, a2b, a3w, a3b);
    k_softmax<<<2 * NNODE, 256>>>(outSup, writeSup);
    // A^2 for each support (into Scat column blocks)
    gemm_kernel<<<dim3(8, 8), 256>>>(pScat, pScat, pScat + 500, 500, 500, 500, 2000, 2000, 2000);
    gemm_kernel<<<dim3(8, 8), 256>>>(pScat + 1000, pScat + 1000, pScat + 1500, 500, 500, 500, 2000, 2000, 2000);
    // input split + enter conv
    k_tmp<<<dim3(TT, BB), 64>>>(inputs, factor);
    k_enter<<<dim3(4, RFh, BB), 128>>>(inputs, factor, enter_w, enter_b, pX0);

    static const int Tin[LL] = {13, 12, 10, 9, 7, 6, 4, 3};
    static const int Dd[LL]  = {1, 2, 1, 2, 1, 2, 1, 2};
    static const int To[LL]  = {12, 10, 9, 7, 6, 4, 3, 1};
    float* Xc = pX0;
    float* Xn = pX1;
    for (int i = 0; i < LL; i++) {
        k_gatefilter<<<dim3(4, To[i], BB), 128>>>(Xc, pXG,
            filt_w + i * 2048, filt_b + i * 32, gate_w + i * 2048, gate_b + i * 32,
            Tin[i], To[i], Dd[i]);
        k_skip<<<dim3(63, BB), 256>>>(pXG, pSkip, skp_w + i * 8192, skp_b + i * 256,
                                      To[i], (i == 0) ? 1 : 0);
        if (i < LL - 1) {   // layer 8's graph_conv/BN output is dead code
            int M = BB * 32 * To[i];
            gemm_kernel<<<dim3(32, (M + 63) / 64), 256>>>(pXG, pScat, pY, M, 2000, 500, 500, 2000, 2000);
            k_gcres<<<dim3(4, To[i], BB), 128>>>(pXG, pY, Xc, Xn,
                gc_w + i * 5120, gc_b + i * 32, pStats + i * 64, Tin[i], To[i], Dd[i]);
            int tot = BB * 32 * To[i] * NNODE;
            k_bnnorm<<<(tot + 255) / 256, 256>>>(Xn, pStats + i * 64, bn_g + i * 32, bn_b + i * 32, To[i]);
            float* t = Xc; Xc = Xn; Xn = t;
        }
    }
    // output head
    k_transpose_skip<<<dim3(16, 8, BB), dim3(32, 32)>>>(pSkip, pSrelu);
    k_transpose_o1w<<<(NENDC * NSKIPC + 255) / 256, 256>>>(o1w, pO1T);
    gemm_kernel<<<dim3(8, 250), 256>>>(pSrelu, pO1T, pY, BB * NNODE, NENDC, NSKIPC, NSKIPC, NENDC, NENDC);
    k_headfinal<<<BB * NNODE, 128>>>(pY, o1b, o2w, o2b, out);
}

// round 2
// speedup vs baseline: 1.1194x; 1.1194x over previous
#include <cuda_runtime.h>
#include <math.h>
#include <stdint.h>

// ---------------- static problem config ----------------
#define BB 32
#define TT 12
#define NNODE 500
#define NSKIPC 256
#define NENDC 512
#define NPREDC 12
#define LL 8
#define RFh 13
#define BN_EPS 1e-5f

// ---------------- device scratch ----------------
__device__ float g_v[NNODE * 32];
__device__ float g_P[NNODE * 64];
__device__ float g_Q[NNODE * 64];
__device__ float g_eraw[2 * NNODE * NNODE];
__device__ float g_Scat[NNODE * 2000];            // [v][ A0 | A0^2 | A1 | A1^2 ]
__device__ float g_tmp[BB * TT * 32 * 2];
__device__ float g_X0[BB * 32 * RFh * NNODE];
__device__ float g_X1[BB * 32 * RFh * NNODE];
__device__ float g_XG[BB * 32 * 12 * NNODE];
__device__ float g_Y[12288 * 2000];               // diffusion outputs; reused as head hidden H
__device__ float g_skip[BB * NSKIPC * NNODE];
__device__ float g_Srelu[BB * NNODE * NSKIPC];
__device__ float g_o1wT[NSKIPC * NENDC];
__device__ float g_part[1536 * 64];               // per-block BN partial sums
__device__ float g_bnab[64];                      // fused BN scale/shift

// ---------------- adjacency ----------------
__global__ void k_v(const float* __restrict__ factor, const float* __restrict__ map_w,
                    const float* __restrict__ map_b) {
    __shared__ float f[32];
    int n = blockIdx.x, d = threadIdx.x;
    f[d] = factor[n * 32 + d];
    __syncthreads();
    float acc = map_b[d];
#pragma unroll
    for (int u = 0; u < 32; u++) acc += f[u] * map_w[u * 32 + d];
    g_v[n * 32 + d] = fmaxf(acc, 0.f);
}

__global__ void k_pq(const float* __restrict__ a1w, const float* __restrict__ a1b) {
    __shared__ float vv[32];
    int j = blockIdx.x, h = threadIdx.x;
    if (h < 32) vv[h] = g_v[j * 32 + h];
    __syncthreads();
    float p = 0.f, q = a1b[h];
#pragma unroll
    for (int d = 0; d < 32; d++) {
        p += vv[d] * a1w[d * 64 + h];
        q += vv[d] * a1w[(32 + d) * 64 + h];
    }
    g_P[j * 64 + h] = p;
    g_Q[j * 64 + h] = q;
}

__global__ void k_adjmlp(const float* __restrict__ a2w, const float* __restrict__ a2b,
                         const float* __restrict__ a3w, const float* __restrict__ a3b) {
    __shared__ float Pt[128][65];
    __shared__ float sA2[64][32];
    __shared__ float sQ[64];
    __shared__ float sA3[64];
    __shared__ float sA2b[32];
    __shared__ float sA3b[2];
    int i = blockIdx.x, tid = threadIdx.x;
    for (int k = tid; k < 64 * 32; k += 128) sA2[k / 32][k % 32] = a2w[k];
    if (tid < 64) { sQ[tid] = g_Q[i * 64 + tid]; sA3[tid] = a3w[tid]; }
    if (tid < 32) sA2b[tid] = a2b[tid];
    if (tid < 2) sA3b[tid] = a3b[tid];
    for (int j0 = 0; j0 < NNODE; j0 += 128) {
        __syncthreads();
        int cnt = min(128, NNODE - j0);
        for (int k = tid; k < cnt * 64; k += 128)
            Pt[k / 64][k % 64] = g_P[(j0 + (k / 64)) * 64 + (k % 64)];
        __syncthreads();
        if (tid < cnt) {
            int j = j0 + tid;
            float h1[64];
#pragma unroll
            for (int h = 0; h < 64; h++) h1[h] = fmaxf(Pt[tid][h] + sQ[h], 0.f);
            float e0 = sA3b[0], e1 = sA3b[1];
#pragma unroll
            for (int c = 0; c < 32; c++) {
                float acc = sA2b[c];
#pragma unroll
                for (int h = 0; h < 64; h++) acc += h1[h] * sA2[h][c];
                acc = fmaxf(acc, 0.f);
                e0 += acc * sA3[c * 2];
                e1 += acc * sA3[c * 2 + 1];
            }
            g_eraw[i * NNODE + j] = e0;
            g_eraw[NNODE * NNODE + i * NNODE + j] = e1;
        }
    }
}

__global__ void k_softmax(float* __restrict__ outSup, int writeSup) {
    int bid = blockIdx.x;
    int e = bid / NNODE, i = bid % NNODE;
    const float* row = g_eraw + e * NNODE * NNODE + i * NNODE;
    __shared__ float red[256];
    int tid = threadIdx.x;
    float m = -1e30f;
    for (int j = tid; j < NNODE; j += 256) m = fmaxf(m, row[j]);
    red[tid] = m; __syncthreads();
    for (int s = 128; s > 0; s >>= 1) { if (tid < s) red[tid] = fmaxf(red[tid], red[tid + s]); __syncthreads(); }
    m = red[0]; __syncthreads();
    float sum = 0.f;
    for (int j = tid; j < NNODE; j += 256) sum += expf(row[j] - m);
    red[tid] = sum; __syncthreads();
    for (int s = 128; s > 0; s >>= 1) { if (tid < s) red[tid] += red[tid + s]; __syncthreads(); }
    float inv = 1.f / red[0];
    for (int j = tid; j < NNODE; j += 256) {
        float p = expf(row[j] - m) * inv;
        if (j == i) p = fmaxf(p, 1.f);
        g_Scat[i * 2000 + e * 1000 + j] = p;
        if (writeSup) outSup[(e * NNODE + i) * NNODE + j] = p;
    }
}

// ---------------- input split + enter ----------------
__global__ void k_tmp(const float* __restrict__ inputs, const float* __restrict__ factor) {
    int t = blockIdx.x, b = blockIdx.y, tid = threadIdx.x;
    int u = tid / 2, f = tid % 2;
    const float* inp = inputs + ((size_t)(b * TT + t) * NNODE) * 2 + f;
    float acc = 0.f;
    for (int n = 0; n < NNODE; n++) acc += inp[n * 2] * factor[n * 32 + u];
    g_tmp[(b * TT + t) * 64 + tid] = acc;
}

__global__ void k_enter(const float* __restrict__ inputs, const float* __restrict__ factor,
                        const float* __restrict__ ew, const float* __restrict__ eb,
                        float* __restrict__ X0) {
    __shared__ float sw[128], sb[32], stmp[64];
    int b = blockIdx.z, tp = blockIdx.y;
    int tid = threadIdx.x;
    if (tid < 128) sw[tid] = ew[tid];
    if (tid < 32) sb[tid] = eb[tid];
    if (tp > 0 && tid < 64) stmp[tid] = g_tmp[(b * TT + (tp - 1)) * 64 + tid];
    __syncthreads();
    int n = blockIdx.x * 128 + tid;
    if (n >= NNODE) return;
    if (tp == 0) {
#pragma unroll
        for (int o = 0; o < 32; o++)
            X0[((size_t)(b * 32 + o) * RFh + 0) * NNODE + n] = sb[o];
    } else {
        int t = tp - 1;
        float s0 = 0.f, s1 = 0.f;
#pragma unroll
        for (int u = 0; u < 32; u++) {
            float fv = factor[n * 32 + u];
            s0 += fv * stmp[u * 2];
            s1 += fv * stmp[u * 2 + 1];
        }
        float i0 = inputs[((size_t)(b * TT + t) * NNODE + n) * 2 + 0];
        float i1 = inputs[((size_t)(b * TT + t) * NNODE + n) * 2 + 1];
        float r0 = i0 - s0, r1 = i1 - s1;
#pragma unroll
        for (int o = 0; o < 32; o++) {
            float v = sb[o] + sw[o * 4] * s0 + sw[o * 4 + 1] * s1 + sw[o * 4 + 2] * r0 + sw[o * 4 + 3] * r1;
            X0[((size_t)(b * 32 + o) * RFh + tp) * NNODE + n] = v;
        }
    }
}

// ---------------- gated dilated temporal conv ----------------
__global__ void k_gatefilter(const float* __restrict__ X, float* __restrict__ XG,
                             const float* __restrict__ fw, const float* __restrict__ fb,
                             const float* __restrict__ gw, const float* __restrict__ gb,
                             int Tin, int Tout, int dd) {
    __shared__ float swf[2048], swg[2048], sfb[32], sgb[32];
    int tid = threadIdx.x;
    for (int idx = tid; idx < 2048; idx += 128) {
        int c = idx >> 6, r = idx & 63, o = r >> 1, kk = r & 1;
        swf[idx] = fw[(o << 6) + (c << 1) + kk];
        swg[idx] = gw[(o << 6) + (c << 1) + kk];
    }
    if (tid < 32) { sfb[tid] = fb[tid]; sgb[tid] = gb[tid]; }
    __syncthreads();
    int n = blockIdx.x * 128 + tid;
    if (n >= NNODE) return;
    int t = blockIdx.y, b = blockIdx.z;
    float fa[32], ga[32];
#pragma unroll
    for (int o = 0; o < 32; o++) { fa[o] = sfb[o]; ga[o] = sgb[o]; }
    const float* Xb = X + (size_t)(b * 32) * Tin * NNODE + n;
    for (int c = 0; c < 32; c++) {
        float xa = Xb[(size_t)(c * Tin + t) * NNODE];
        float xb = Xb[(size_t)(c * Tin + t + dd) * NNODE];
        const float4* wf4 = (const float4*)&swf[c * 64];
        const float4* wg4 = (const float4*)&swg[c * 64];
#pragma unroll
        for (int o2 = 0; o2 < 16; o2++) {
            float4 wf = wf4[o2];
            fa[o2 * 2 + 0] += wf.x * xa + wf.y * xb;
            fa[o2 * 2 + 1] += wf.z * xa + wf.w * xb;
            float4 wg = wg4[o2];
            ga[o2 * 2 + 0] += wg.x * xa + wg.y * xb;
            ga[o2 * 2 + 1] += wg.z * xa + wg.w * xb;
        }
    }
#pragma unroll
    for (int o = 0; o < 32; o++) {
        float s = 1.f / (1.f + expf(-ga[o]));
        XG[((size_t)(b * 32 + o) * Tout + t) * NNODE + n] = tanhf(fa[o]) * s;
    }
}

// ---------------- skip (last timestep only) ----------------
__global__ void k_skip(const float* __restrict__ XG, float* __restrict__ skip,
                       const float* __restrict__ sw_g, const float* __restrict__ sb_g,
                       int Tout, int first) {
    __shared__ float xs[8][32];
    int b = blockIdx.y;
    int n0 = blockIdx.x * 8;
    int tid = threadIdx.x;
    {
        int nn = tid / 32, c = tid % 32;
        int n = n0 + nn;
        xs[nn][c] = (n < NNODE) ? XG[((size_t)(b * 32 + c) * Tout + (Tout - 1)) * NNODE + n] : 0.f;
    }
    __syncthreads();
    int o = tid;
    float w[32];
#pragma unroll
    for (int c = 0; c < 32; c++) w[c] = sw_g[o * 32 + c];
    float bias = sb_g[o];
#pragma unroll
    for (int nn = 0; nn < 8; nn++) {
        int n = n0 + nn;
        if (n >= NNODE) break;
        float acc = bias;
#pragma unroll
        for (int c = 0; c < 32; c++) acc += w[c] * xs[nn][c];
        size_t idx = (size_t)(b * NSKIPC + o) * NNODE + n;
        if (first) skip[idx] = acc;
        else skip[idx] += acc;
    }
}

// ---------------- SGEMM v2: 128x128x8, 8x8/thread, double-buffered ----------------
__global__ __launch_bounds__(256)
void sgemm(const float* __restrict__ A, const float* __restrict__ B, float* __restrict__ C,
           int M, int N, int K, int lda, int ldb, int ldc,
           int sA, int sB, int sC) {
    __shared__ float As[2][8][128];
    __shared__ float Bs[2][8][128];
    A += (size_t)blockIdx.z * sA;
    B += (size_t)blockIdx.z * sB;
    C += (size_t)blockIdx.z * sC;
    int tid = threadIdx.x;
    int m0 = blockIdx.y * 128, n0 = blockIdx.x * 128;
    int arow = tid >> 1, acol = (tid & 1) * 4;
    int brow = tid >> 5, bcol = (tid & 31) * 4;
    int tx = tid & 15, ty = tid >> 4;
    float acc[8][8];
#pragma unroll
    for (int i = 0; i < 8; i++)
#pragma unroll
        for (int j = 0; j < 8; j++) acc[i][j] = 0.f;

    int NKT = (K + 7) / 8;
    float4 av, bv;
    // prologue load kt=0
    {
        int k = 0;
        av = make_float4(0.f, 0.f, 0.f, 0.f);
        int ar = m0 + arow;
        if (ar < M) {
            int c0 = k + acol;
            if (c0 + 3 < K) av = *(const float4*)(A + (size_t)ar * lda + c0);
            else {
                if (c0 + 0 < K) av.x = A[(size_t)ar * lda + c0 + 0];
                if (c0 + 1 < K) av.y = A[(size_t)ar * lda + c0 + 1];
                if (c0 + 2 < K) av.z = A[(size_t)ar * lda + c0 + 2];
                if (c0 + 3 < K) av.w = A[(size_t)ar * lda + c0 + 3];
            }
        }
        bv = make_float4(0.f, 0.f, 0.f, 0.f);
        int br = k + brow, bc = n0 + bcol;
        if (br < K) {
            if (bc + 3 < N) bv = *(const float4*)(B + (size_t)br * ldb + bc);
            else {
                if (bc + 0 < N) bv.x = B[(size_t)br * ldb + bc + 0];
                if (bc + 1 < N) bv.y = B[(size_t)br * ldb + bc + 1];
                if (bc + 2 < N) bv.z = B[(size_t)br * ldb + bc + 2];
                if (bc + 3 < N) bv.w = B[(size_t)br * ldb + bc + 3];
            }
        }
        As[0][acol + 0][arow] = av.x;
        As[0][acol + 1][arow] = av.y;
        As[0][acol + 2][arow] = av.z;
        As[0][acol + 3][arow] = av.w;
        *(float4*)&Bs[0][brow][bcol] = bv;
    }
    __syncthreads();

    for (int kt = 0; kt < NKT; kt++) {
        int cur = kt & 1, nxt = cur ^ 1;
        bool hasNext = (kt + 1 < NKT);
        if (hasNext) {
            int k = (kt + 1) * 8;
            av = make_float4(0.f, 0.f, 0.f, 0.f);
            int ar = m0 + arow;
            if (ar < M) {
                int c0 = k + acol;
                if (c0 + 3 < K) av = *(const float4*)(A + (size_t)ar * lda + c0);
                else {
                    if (c0 + 0 < K) av.x = A[(size_t)ar * lda + c0 + 0];
                    if (c0 + 1 < K) av.y = A[(size_t)ar * lda + c0 + 1];
                    if (c0 + 2 < K) av.z = A[(size_t)ar * lda + c0 + 2];
                    if (c0 + 3 < K) av.w = A[(size_t)ar * lda + c0 + 3];
                }
            }
            bv = make_float4(0.f, 0.f, 0.f, 0.f);
            int br = k + brow, bc = n0 + bcol;
            if (br < K) {
                if (bc + 3 < N) bv = *(const float4*)(B + (size_t)br * ldb + bc);
                else {
                    if (bc + 0 < N) bv.x = B[(size_t)br * ldb + bc + 0];
                    if (bc + 1 < N) bv.y = B[(size_t)br * ldb + bc + 1];
                    if (bc + 2 < N) bv.z = B[(size_t)br * ldb + bc + 2];
                    if (bc + 3 < N) bv.w = B[(size_t)br * ldb + bc + 3];
                }
            }
        }
#pragma unroll
        for (int kk = 0; kk < 8; kk++) {
            float4 a0 = *(const float4*)&As[cur][kk][ty * 8];
            float4 a1 = *(const float4*)&As[cur][kk][ty * 8 + 4];
            float4 b0 = *(const float4*)&Bs[cur][kk][tx * 8];
            float4 b1 = *(const float4*)&Bs[cur][kk][tx * 8 + 4];
            float a[8] = {a0.x, a0.y, a0.z, a0.w, a1.x, a1.y, a1.z, a1.w};
            float b[8] = {b0.x, b0.y, b0.z, b0.w, b1.x, b1.y, b1.z, b1.w};
#pragma unroll
            for (int i = 0; i < 8; i++)
#pragma unroll
                for (int j = 0; j < 8; j++) acc[i][j] += a[i] * b[j];
        }
        if (hasNext) {
            __syncthreads();
            As[nxt][acol + 0][arow] = av.x;
            As[nxt][acol + 1][arow] = av.y;
            As[nxt][acol + 2][arow] = av.z;
            As[nxt][acol + 3][arow] = av.w;
            *(float4*)&Bs[nxt][brow][bcol] = bv;
            __syncthreads();
        }
    }
#pragma unroll
    for (int i = 0; i < 8; i++) {
        int row = m0 + ty * 8 + i;
        if (row >= M) continue;
        float* Cr = C + (size_t)row * ldc;
        int col0 = n0 + tx * 8;
        if (col0 + 7 < N) {
            *(float4*)(Cr + col0) = make_float4(acc[i][0], acc[i][1], acc[i][2], acc[i][3]);
            *(float4*)(Cr + col0 + 4) = make_float4(acc[i][4], acc[i][5], acc[i][6], acc[i][7]);
        } else {
#pragma unroll
            for (int j = 0; j < 8; j++)
                if (col0 + j < N) Cr[col0 + j] = acc[i][j];
        }
    }
}

// ---------------- gc 1x1 + residual + BN partial stats ----------------
__global__ void k_gcres(const float* __restrict__ XG, const float* __restrict__ Y,
                        const float* __restrict__ Xc, float* __restrict__ Xn,
                        const float* __restrict__ gcw, const float* __restrict__ gcb,
                        float* __restrict__ part, int Tin, int Tout, int dd) {
    __shared__ float swg[160 * 32];
    __shared__ float sgb[32];
    __shared__ float sredS[4][32];
    __shared__ float sredQ[4][32];
    int tid = threadIdx.x;
    for (int idx = tid; idx < 160 * 32; idx += 128) {
        int c = idx / 32, o = idx % 32;
        swg[idx] = gcw[o * 160 + c];
    }
    if (tid < 32) sgb[tid] = gcb[tid];
    __syncthreads();
    int n = blockIdx.x * 128 + tid;
    int t = blockIdx.y, b = blockIdx.z;
    bool active = (n < NNODE);
    float acc[32];
#pragma unroll
    for (int o = 0; o < 32; o++) acc[o] = active ? sgb[o] : 0.f;
    if (active) {
        for (int c = 0; c < 32; c++) {
            float val = XG[((size_t)(b * 32 + c) * Tout + t) * NNODE + n];
            const float4* w4 = (const float4*)&swg[c * 32];
#pragma unroll
            for (int q = 0; q < 8; q++) {
                float4 w = w4[q];
                acc[q * 4 + 0] += w.x * val; acc[q * 4 + 1] += w.y * val;
                acc[q * 4 + 2] += w.z * val; acc[q * 4 + 3] += w.w * val;
            }
        }
        for (int e = 0; e < 4; e++) {
            for (int c = 0; c < 32; c++) {
                size_t m = (size_t)(b * 32 + c) * Tout + t;
                float val = Y[m * 2000 + e * 500 + n];
                const float4* w4 = (const float4*)&swg[(32 + e * 32 + c) * 32];
#pragma unroll
                for (int q = 0; q < 8; q++) {
                    float4 w = w4[q];
                    acc[q * 4 + 0] += w.x * val; acc[q * 4 + 1] += w.y * val;
                    acc[q * 4 + 2] += w.z * val; acc[q * 4 + 3] += w.w * val;
                }
            }
        }
#pragma unroll
        for (int o = 0; o < 32; o++) {
            acc[o] += Xc[((size_t)(b * 32 + o) * Tin + t + dd) * NNODE + n];
            Xn[((size_t)(b * 32 + o) * Tout + t) * NNODE + n] = acc[o];
        }
    }
    int lane = tid & 31, warp = tid >> 5;
#pragma unroll
    for (int o = 0; o < 32; o++) {
        float s = active ? acc[o] : 0.f;
        float q = s * s;
#pragma unroll
        for (int off = 16; off; off >>= 1) {
            s += __shfl_down_sync(0xffffffffu, s, off);
            q += __shfl_down_sync(0xffffffffu, q, off);
        }
        if (lane == 0) { sredS[warp][o] = s; sredQ[warp][o] = q; }
    }
    __syncthreads();
    if (tid < 64) {
        int o = tid & 31;
        bool isq = (tid >= 32);
        float v = 0.f;
#pragma unroll
        for (int w = 0; w < 4; w++) v += (isq ? sredQ[w][o] : sredS[w][o]);
        size_t bidx = (size_t)(blockIdx.z * gridDim.y + blockIdx.y) * gridDim.x + blockIdx.x;
        part[bidx * 64 + tid] = v;
    }
}

// reduce partials -> fused BN scale/shift
__global__ void k_redstats(const float* __restrict__ part, int nblk, float cnt,
                           const float* __restrict__ g, const float* __restrict__ bta,
                           float* __restrict__ ab) {
    int c = blockIdx.x;       // 0..31
    int tid = threadIdx.x;    // 256
    double s = 0.0, q = 0.0;
    for (int i = tid; i < nblk; i += 256) {
        s += (double)part[(size_t)i * 64 + c];
        q += (double)part[(size_t)i * 64 + 32 + c];
    }
    __shared__ double rs[256], rq[256];
    rs[tid] = s; rq[tid] = q;
    __syncthreads();
    for (int st = 128; st > 0; st >>= 1) {
        if (tid < st) { rs[tid] += rs[tid + st]; rq[tid] += rq[tid + st]; }
        __syncthreads();
    }
    if (tid == 0) {
        float mean = (float)(rs[0] / cnt);
        float var = (float)(rq[0] / cnt) - mean * mean;
        float a = g[c] * rsqrtf(var + BN_EPS);
        ab[c] = a;
        ab[32 + c] = bta[c] - mean * a;
    }
}

__global__ void k_bnnorm(float* __restrict__ X, const float* __restrict__ ab, int Tout) {
    int idx = blockIdx.x * 256 + threadIdx.x;
    int total = BB * 32 * Tout * NNODE;
    if (idx >= total) return;
    int c = (idx / (Tout * NNODE)) % 32;
    X[idx] = X[idx] * ab[c] + ab[32 + c];
}

// ---------------- output head ----------------
__global__ void k_transpose_skip(const float* __restrict__ skip, float* __restrict__ Srelu) {
    __shared__ float tile[32][33];
    int b = blockIdx.z;
    int n0 = blockIdx.x * 32, c0 = blockIdx.y * 32;
    int n = n0 + threadIdx.x, c = c0 + threadIdx.y;
    tile[threadIdx.y][threadIdx.x] = (n < NNODE) ? skip[(size_t)(b * NSKIPC + c) * NNODE + n] : 0.f;
    __syncthreads();
    int n2 = n0 + threadIdx.y, c2 = c0 + threadIdx.x;
    if (n2 < NNODE)
        Srelu[(size_t)(b * NNODE + n2) * NSKIPC + c2] = fmaxf(tile[threadIdx.x][threadIdx.y], 0.f);
}

__global__ void k_transpose_o1w(const float* __restrict__ o1w, float* __restrict__ o1wT) {
    int idx = blockIdx.x * 256 + threadIdx.x;
    if (idx >= NENDC * NSKIPC) return;
    int h = idx / NSKIPC, c = idx % NSKIPC;
    o1wT[c * NENDC + h] = o1w[idx];
}

__global__ void k_headfinal(const float* __restrict__ H, const float* __restrict__ o1b,
                            const float* __restrict__ o2w, const float* __restrict__ o2b,
                            float* __restrict__ out) {
    int warp = threadIdx.x >> 5, lane = threadIdx.x & 31;
    int row = blockIdx.x * 4 + warp;
    if (row >= BB * NNODE) return;
    int b = row / NNODE, n = row % NNODE;
    const float* Hr = H + (size_t)row * NENDC;
    float h[16];
#pragma unroll
    for (int i = 0; i < 16; i++)
        h[i] = fmaxf(Hr[lane + i * 32] + o1b[lane + i * 32], 0.f);
#pragma unroll
    for (int p = 0; p < NPREDC; p++) {
        float acc = 0.f;
#pragma unroll
        for (int i = 0; i < 16; i++) acc += o2w[p * NENDC + lane + i * 32] * h[i];
#pragma unroll
        for (int off = 16; off; off >>= 1) acc += __shfl_down_sync(0xffffffffu, acc, off);
        if (lane == 0) out[(size_t)(b * NPREDC + p) * NNODE + n] = acc + o2b[p];
    }
}

// ---------------- host launcher ----------------
extern "C" void kernel_launch(void* const* d_in, const int* in_sizes, int n_in,
                              void* d_out, int out_size) {
    const float* inputs = (const float*)d_in[0];
    const float* factor = (const float*)d_in[1];
    const float* map_w  = (const float*)d_in[2];
    const float* map_b  = (const float*)d_in[3];
    const float* a1w    = (const float*)d_in[4];
    const float* a1b    = (const float*)d_in[5];
    const float* a2w    = (const float*)d_in[6];
    const float* a2b    = (const float*)d_in[7];
    const float* a3w    = (const float*)d_in[8];
    const float* a3b    = (const float*)d_in[9];
    const float* enter_w = (const float*)d_in[10];
    const float* enter_b = (const float*)d_in[11];
    const float* filt_w = (const float*)d_in[12];
    const float* filt_b = (const float*)d_in[13];
    const float* gate_w = (const float*)d_in[14];
    const float* gate_b = (const float*)d_in[15];
    const float* skp_w  = (const float*)d_in[16];
    const float* skp_b  = (const float*)d_in[17];
    const float* gc_w   = (const float*)d_in[18];
    const float* gc_b   = (const float*)d_in[19];
    const float* bn_g   = (const float*)d_in[20];
    const float* bn_b   = (const float*)d_in[21];
    const float* o1w    = (const float*)d_in[22];
    const float* o1b    = (const float*)d_in[23];
    const float* o2w    = (const float*)d_in[24];
    const float* o2b    = (const float*)d_in[25];

    float *pScat, *pY, *pX0, *pX1, *pXG, *pSkip, *pSrelu, *pO1T, *pPart, *pAB;
    cudaGetSymbolAddress((void**)&pScat, g_Scat);
    cudaGetSymbolAddress((void**)&pY, g_Y);
    cudaGetSymbolAddress((void**)&pX0, g_X0);
    cudaGetSymbolAddress((void**)&pX1, g_X1);
    cudaGetSymbolAddress((void**)&pXG, g_XG);
    cudaGetSymbolAddress((void**)&pSkip, g_skip);
    cudaGetSymbolAddress((void**)&pSrelu, g_Srelu);
    cudaGetSymbolAddress((void**)&pO1T, g_o1wT);
    cudaGetSymbolAddress((void**)&pPart, g_part);
    cudaGetSymbolAddress((void**)&pAB, g_bnab);

    float* out = (float*)d_out;
    const int ySize = BB * NPREDC * NNODE;
    const int supSize = 2 * NNODE * NNODE;
    int writeSup = (out_size >= ySize + supSize) ? 1 : 0;
    float* outSup = out + ySize;

    // adaptive adjacency
    k_v<<<NNODE, 32>>>(factor, map_w, map_b);
    k_pq<<<NNODE, 64>>>(a1w, a1b);
    k_adjmlp<<<NNODE, 128>>>(a2w, a2b, a3w, a3b);
    k_softmax<<<2 * NNODE, 256>>>(outSup, writeSup);
    // A^2 for both supports in one batched launch
    sgemm<<<dim3(4, 4, 2), 256>>>(pScat, pScat, pScat + 500, 500, 500, 500, 2000, 2000, 2000,
                                  1000, 1000, 1000);
    // input split + enter conv
    k_tmp<<<dim3(TT, BB), 64>>>(inputs, factor);
    k_enter<<<dim3(4, RFh, BB), 128>>>(inputs, factor, enter_w, enter_b, pX0);

    static const int Tin[LL] = {13, 12, 10, 9, 7, 6, 4, 3};
    static const int Dd[LL]  = {1, 2, 1, 2, 1, 2, 1, 2};
    static const int To[LL]  = {12, 10, 9, 7, 6, 4, 3, 1};
    float* Xc = pX0;
    float* Xn = pX1;
    for (int i = 0; i < LL; i++) {
        k_gatefilter<<<dim3(4, To[i], BB), 128>>>(Xc, pXG,
            filt_w + i * 2048, filt_b + i * 32, gate_w + i * 2048, gate_b + i * 32,
            Tin[i], To[i], Dd[i]);
        k_skip<<<dim3(63, BB), 256>>>(pXG, pSkip, skp_w + i * 8192, skp_b + i * 256,
                                      To[i], (i == 0) ? 1 : 0);
        if (i < LL - 1) {   // layer 8's graph_conv/BN output is dead code
            int M = BB * 32 * To[i];
            sgemm<<<dim3(16, (M + 127) / 128), 256>>>(pXG, pScat, pY, M, 2000, 500,
                                                      500, 2000, 2000, 0, 0, 0);
            int nblk = 4 * To[i] * BB;
            k_gcres<<<dim3(4, To[i], BB), 128>>>(pXG, pY, Xc, Xn,
                gc_w + i * 5120, gc_b + i * 32, pPart, Tin[i], To[i], Dd[i]);
            k_redstats<<<32, 256>>>(pPart, nblk, (float)(BB * To[i] * NNODE),
                                    bn_g + i * 32, bn_b + i * 32, pAB);
            int tot = BB * 32 * To[i] * NNODE;
            k_bnnorm<<<(tot + 255) / 256, 256>>>(Xn, pAB, To[i]);
            float* t = Xc; Xc = Xn; Xn = t;
        }
    }
    // output head
    k_transpose_skip<<<dim3(16, 8, BB), dim3(32, 32)>>>(pSkip, pSrelu);
    k_transpose_o1w<<<(NENDC * NSKIPC + 255) / 256, 256>>>(o1w, pO1T);
    sgemm<<<dim3(4, 125), 256>>>(pSrelu, pO1T, pY, BB * NNODE, NENDC, NSKIPC,
                                 NSKIPC, NENDC, NENDC, 0, 0, 0);
    k_headfinal<<<(BB * NNODE + 3) / 4, 128>>>(pY, o1b, o2w, o2b, out);
}

// round 3
// speedup vs baseline: 1.1416x; 1.0198x over previous
#include <cuda_runtime.h>
#include <math.h>
#include <stdint.h>

// ---------------- static problem config ----------------
#define BB 32
#define TT 12
#define NNODE 500
#define NSKIPC 256
#define NENDC 512
#define NPREDC 12
#define LL 8
#define RFh 13
#define BN_EPS 1e-5f

typedef unsigned long long ull;

__device__ __forceinline__ ull pack2(float lo, float hi) {
    ull r; asm("mov.b64 %0,{%1,%2};" : "=l"(r) : "f"(lo), "f"(hi)); return r;
}
__device__ __forceinline__ ull fma2(ull a, ull b, ull c) {
    ull d; asm("fma.rn.f32x2 %0,%1,%2,%3;" : "=l"(d) : "l"(a), "l"(b), "l"(c)); return d;
}
__device__ __forceinline__ void unpack2(ull v, float& lo, float& hi) {
    asm("mov.b64 {%0,%1},%2;" : "=f"(lo), "=f"(hi) : "l"(v));
}

// ---------------- device scratch ----------------
__device__ float g_v[NNODE * 32];
__device__ float g_P[NNODE * 64];
__device__ float g_Q[NNODE * 64];
__device__ float g_eraw[2 * NNODE * NNODE];
__device__ float g_Scat[NNODE * 2000];            // [v][ A0 | A0^2 | A1 | A1^2 ]
__device__ float g_tmp[BB * TT * 32 * 2];
__device__ float g_X0[BB * 32 * RFh * NNODE];
__device__ float g_X1[BB * 32 * RFh * NNODE];
__device__ float g_XG[BB * 32 * 12 * NNODE];
__device__ float g_Y[12288 * 2000];               // diffusion outputs; reused as head hidden H
__device__ float g_skip[BB * NSKIPC * NNODE];
__device__ float g_Srelu[BB * NNODE * NSKIPC];
__device__ float g_o1wT[NSKIPC * NENDC];
__device__ float g_part[1536 * 64];               // per-block BN partial sums
__device__ float g_bnab[64];                      // fused BN scale/shift

// ---------------- adjacency ----------------
__global__ void k_v(const float* __restrict__ factor, const float* __restrict__ map_w,
                    const float* __restrict__ map_b) {
    __shared__ float f[32];
    int n = blockIdx.x, d = threadIdx.x;
    f[d] = factor[n * 32 + d];
    __syncthreads();
    float acc = map_b[d];
#pragma unroll
    for (int u = 0; u < 32; u++) acc += f[u] * map_w[u * 32 + d];
    g_v[n * 32 + d] = fmaxf(acc, 0.f);
}

__global__ void k_pq(const float* __restrict__ a1w, const float* __restrict__ a1b) {
    __shared__ float vv[32];
    int j = blockIdx.x, h = threadIdx.x;
    if (h < 32) vv[h] = g_v[j * 32 + h];
    __syncthreads();
    float p = 0.f, q = a1b[h];
#pragma unroll
    for (int d = 0; d < 32; d++) {
        p += vv[d] * a1w[d * 64 + h];
        q += vv[d] * a1w[(32 + d) * 64 + h];
    }
    g_P[j * 64 + h] = p;
    g_Q[j * 64 + h] = q;
}

__global__ void k_adjmlp(const float* __restrict__ a2w, const float* __restrict__ a2b,
                         const float* __restrict__ a3w, const float* __restrict__ a3b) {
    __shared__ float Pt[128][65];
    __shared__ __align__(16) float sA2[64][32];
    __shared__ float sQ[64];
    __shared__ float sA3[64];
    __shared__ float sA2b[32];
    __shared__ float sA3b[2];
    int i = blockIdx.x, tid = threadIdx.x;
    for (int k = tid; k < 64 * 32; k += 128) sA2[k / 32][k % 32] = a2w[k];
    if (tid < 64) { sQ[tid] = g_Q[i * 64 + tid]; sA3[tid] = a3w[tid]; }
    if (tid < 32) sA2b[tid] = a2b[tid];
    if (tid < 2) sA3b[tid] = a3b[tid];
    for (int j0 = 0; j0 < NNODE; j0 += 128) {
        __syncthreads();
        int cnt = min(128, NNODE - j0);
        for (int k = tid; k < cnt * 64; k += 128)
            Pt[k / 64][k % 64] = g_P[(j0 + (k / 64)) * 64 + (k % 64)];
        __syncthreads();
        if (tid < cnt) {
            int j = j0 + tid;
            float h1[64];
#pragma unroll
            for (int h = 0; h < 64; h++) h1[h] = fmaxf(Pt[tid][h] + sQ[h], 0.f);
            float e0 = sA3b[0], e1 = sA3b[1];
#pragma unroll
            for (int c = 0; c < 32; c++) {
                float acc = sA2b[c];
#pragma unroll
                for (int h = 0; h < 64; h++) acc += h1[h] * sA2[h][c];
                acc = fmaxf(acc, 0.f);
                e0 += acc * sA3[c * 2];
                e1 += acc * sA3[c * 2 + 1];
            }
            g_eraw[i * NNODE + j] = e0;
            g_eraw[NNODE * NNODE + i * NNODE + j] = e1;
        }
    }
}

__global__ void k_softmax(float* __restrict__ outSup, int writeSup) {
    int bid = blockIdx.x;
    int e = bid / NNODE, i = bid % NNODE;
    const float* row = g_eraw + e * NNODE * NNODE + i * NNODE;
    __shared__ float red[256];
    int tid = threadIdx.x;
    float m = -1e30f;
    for (int j = tid; j < NNODE; j += 256) m = fmaxf(m, row[j]);
    red[tid] = m; __syncthreads();
    for (int s = 128; s > 0; s >>= 1) { if (tid < s) red[tid] = fmaxf(red[tid], red[tid + s]); __syncthreads(); }
    m = red[0]; __syncthreads();
    float sum = 0.f;
    for (int j = tid; j < NNODE; j += 256) sum += expf(row[j] - m);
    red[tid] = sum; __syncthreads();
    for (int s = 128; s > 0; s >>= 1) { if (tid < s) red[tid] += red[tid + s]; __syncthreads(); }
    float inv = 1.f / red[0];
    for (int j = tid; j < NNODE; j += 256) {
        float p = expf(row[j] - m) * inv;
        if (j == i) p = fmaxf(p, 1.f);
        g_Scat[i * 2000 + e * 1000 + j] = p;
        if (writeSup) outSup[(e * NNODE + i) * NNODE + j] = p;
    }
}

// ---------------- input split + enter ----------------
__global__ void k_tmp(const float* __restrict__ inputs, const float* __restrict__ factor) {
    int t = blockIdx.x, b = blockIdx.y, tid = threadIdx.x;
    int u = tid / 2, f = tid % 2;
    const float* inp = inputs + ((size_t)(b * TT + t) * NNODE) * 2 + f;
    float acc = 0.f;
    for (int n = 0; n < NNODE; n++) acc += inp[n * 2] * factor[n * 32 + u];
    g_tmp[(b * TT + t) * 64 + tid] = acc;
}

__global__ void k_enter(const float* __restrict__ inputs, const float* __restrict__ factor,
                        const float* __restrict__ ew, const float* __restrict__ eb,
                        float* __restrict__ X0) {
    __shared__ float sw[128], sb[32], stmp[64];
    int b = blockIdx.z, tp = blockIdx.y;
    int tid = threadIdx.x;
    if (tid < 128) sw[tid] = ew[tid];
    if (tid < 32) sb[tid] = eb[tid];
    if (tp > 0 && tid < 64) stmp[tid] = g_tmp[(b * TT + (tp - 1)) * 64 + tid];
    __syncthreads();
    int n = blockIdx.x * 128 + tid;
    if (n >= NNODE) return;
    if (tp == 0) {
#pragma unroll
        for (int o = 0; o < 32; o++)
            X0[((size_t)(b * 32 + o) * RFh + 0) * NNODE + n] = sb[o];
    } else {
        int t = tp - 1;
        float s0 = 0.f, s1 = 0.f;
#pragma unroll
        for (int u = 0; u < 32; u++) {
            float fv = factor[n * 32 + u];
            s0 += fv * stmp[u * 2];
            s1 += fv * stmp[u * 2 + 1];
        }
        float i0 = inputs[((size_t)(b * TT + t) * NNODE + n) * 2 + 0];
        float i1 = inputs[((size_t)(b * TT + t) * NNODE + n) * 2 + 1];
        float r0 = i0 - s0, r1 = i1 - s1;
#pragma unroll
        for (int o = 0; o < 32; o++) {
            float v = sb[o] + sw[o * 4] * s0 + sw[o * 4 + 1] * s1 + sw[o * 4 + 2] * r0 + sw[o * 4 + 3] * r1;
            X0[((size_t)(b * 32 + o) * RFh + tp) * NNODE + n] = v;
        }
    }
}

// ---------------- gated dilated temporal conv (f32x2) ----------------
// smem weight layout: [c][kk][o] so o-pairs are contiguous
__global__ void k_gatefilter(const float* __restrict__ X, float* __restrict__ XG,
                             const float* __restrict__ fw, const float* __restrict__ fb,
                             const float* __restrict__ gw, const float* __restrict__ gb,
                             int Tin, int Tout, int dd) {
    __shared__ __align__(16) float swf[2048];
    __shared__ __align__(16) float swg[2048];
    __shared__ float sfb[32], sgb[32];
    int tid = threadIdx.x;
    for (int idx = tid; idx < 2048; idx += 128) {
        int c = idx >> 6, r = idx & 63, kk = r >> 5, o = r & 31;
        swf[idx] = fw[(o << 6) + (c << 1) + kk];
        swg[idx] = gw[(o << 6) + (c << 1) + kk];
    }
    if (tid < 32) { sfb[tid] = fb[tid]; sgb[tid] = gb[tid]; }
    __syncthreads();
    int n = blockIdx.x * 128 + tid;
    if (n >= NNODE) return;
    int t = blockIdx.y, b = blockIdx.z;
    ull fa2[16], ga2[16];
#pragma unroll
    for (int p = 0; p < 16; p++) {
        fa2[p] = pack2(sfb[p * 2], sfb[p * 2 + 1]);
        ga2[p] = pack2(sgb[p * 2], sgb[p * 2 + 1]);
    }
    const float* Xb = X + (size_t)(b * 32) * Tin * NNODE + n;
    for (int c = 0; c < 32; c++) {
        float xa = Xb[(size_t)(c * Tin + t) * NNODE];
        float xb = Xb[(size_t)(c * Tin + t + dd) * NNODE];
        ull xad = pack2(xa, xa), xbd = pack2(xb, xb);
        const ull* wf0 = (const ull*)&swf[c * 64];
        const ull* wf1 = (const ull*)&swf[c * 64 + 32];
        const ull* wg0 = (const ull*)&swg[c * 64];
        const ull* wg1 = (const ull*)&swg[c * 64 + 32];
#pragma unroll
        for (int p = 0; p < 16; p++) {
            fa2[p] = fma2(xad, wf0[p], fa2[p]);
            fa2[p] = fma2(xbd, wf1[p], fa2[p]);
            ga2[p] = fma2(xad, wg0[p], ga2[p]);
            ga2[p] = fma2(xbd, wg1[p], ga2[p]);
        }
    }
#pragma unroll
    for (int p = 0; p < 16; p++) {
        float f0, f1, g0, g1;
        unpack2(fa2[p], f0, f1);
        unpack2(ga2[p], g0, g1);
        float s0 = 1.f / (1.f + expf(-g0));
        float s1 = 1.f / (1.f + expf(-g1));
        XG[((size_t)(b * 32 + p * 2 + 0) * Tout + t) * NNODE + n] = tanhf(f0) * s0;
        XG[((size_t)(b * 32 + p * 2 + 1) * Tout + t) * NNODE + n] = tanhf(f1) * s1;
    }
}

// ---------------- skip (last timestep only) ----------------
__global__ void k_skip(const float* __restrict__ XG, float* __restrict__ skip,
                       const float* __restrict__ sw_g, const float* __restrict__ sb_g,
                       int Tout, int first) {
    __shared__ float xs[8][32];
    int b = blockIdx.y;
    int n0 = blockIdx.x * 8;
    int tid = threadIdx.x;
    {
        int nn = tid / 32, c = tid % 32;
        int n = n0 + nn;
        xs[nn][c] = (n < NNODE) ? XG[((size_t)(b * 32 + c) * Tout + (Tout - 1)) * NNODE + n] : 0.f;
    }
    __syncthreads();
    int o = tid;
    float w[32];
#pragma unroll
    for (int c = 0; c < 32; c++) w[c] = sw_g[o * 32 + c];
    float bias = sb_g[o];
#pragma unroll
    for (int nn = 0; nn < 8; nn++) {
        int n = n0 + nn;
        if (n >= NNODE) break;
        float acc = bias;
#pragma unroll
        for (int c = 0; c < 32; c++) acc += w[c] * xs[nn][c];
        size_t idx = (size_t)(b * NSKIPC + o) * NNODE + n;
        if (first) skip[idx] = acc;
        else skip[idx] += acc;
    }
}

// ---------------- SGEMM: 128x128x8, 8x8/thread, double-buffered, f32x2 core ----------------
__global__ __launch_bounds__(256)
void sgemm(const float* __restrict__ A, const float* __restrict__ B, float* __restrict__ C,
           int M, int N, int K, int lda, int ldb, int ldc,
           int sA, int sB, int sC) {
    __shared__ __align__(16) float As[2][8][128];
    __shared__ __align__(16) float Bs[2][8][128];
    A += (size_t)blockIdx.z * sA;
    B += (size_t)blockIdx.z * sB;
    C += (size_t)blockIdx.z * sC;
    int tid = threadIdx.x;
    int m0 = blockIdx.y * 128, n0 = blockIdx.x * 128;
    int arow = tid >> 1, acol = (tid & 1) * 4;
    int brow = tid >> 5, bcol = (tid & 31) * 4;
    int tx = tid & 15, ty = tid >> 4;
    ull acc2[8][4];
#pragma unroll
    for (int i = 0; i < 8; i++)
#pragma unroll
        for (int j = 0; j < 4; j++) acc2[i][j] = pack2(0.f, 0.f);

    int NKT = (K + 7) / 8;
    float4 av, bv;
    {
        int k = 0;
        av = make_float4(0.f, 0.f, 0.f, 0.f);
        int ar = m0 + arow;
        if (ar < M) {
            int c0 = k + acol;
            if (c0 + 3 < K) av = *(const float4*)(A + (size_t)ar * lda + c0);
            else {
                if (c0 + 0 < K) av.x = A[(size_t)ar * lda + c0 + 0];
                if (c0 + 1 < K) av.y = A[(size_t)ar * lda + c0 + 1];
                if (c0 + 2 < K) av.z = A[(size_t)ar * lda + c0 + 2];
                if (c0 + 3 < K) av.w = A[(size_t)ar * lda + c0 + 3];
            }
        }
        bv = make_float4(0.f, 0.f, 0.f, 0.f);
        int br = k + brow, bc = n0 + bcol;
        if (br < K) {
            if (bc + 3 < N) bv = *(const float4*)(B + (size_t)br * ldb + bc);
            else {
                if (bc + 0 < N) bv.x = B[(size_t)br * ldb + bc + 0];
                if (bc + 1 < N) bv.y = B[(size_t)br * ldb + bc + 1];
                if (bc + 2 < N) bv.z = B[(size_t)br * ldb + bc + 2];
                if (bc + 3 < N) bv.w = B[(size_t)br * ldb + bc + 3];
            }
        }
        As[0][acol + 0][arow] = av.x;
        As[0][acol + 1][arow] = av.y;
        As[0][acol + 2][arow] = av.z;
        As[0][acol + 3][arow] = av.w;
        *(float4*)&Bs[0][brow][bcol] = bv;
    }
    __syncthreads();

    for (int kt = 0; kt < NKT; kt++) {
        int cur = kt & 1, nxt = cur ^ 1;
        bool hasNext = (kt + 1 < NKT);
        if (hasNext) {
            int k = (kt + 1) * 8;
            av = make_float4(0.f, 0.f, 0.f, 0.f);
            int ar = m0 + arow;
            if (ar < M) {
                int c0 = k + acol;
                if (c0 + 3 < K) av = *(const float4*)(A + (size_t)ar * lda + c0);
                else {
                    if (c0 + 0 < K) av.x = A[(size_t)ar * lda + c0 + 0];
                    if (c0 + 1 < K) av.y = A[(size_t)ar * lda + c0 + 1];
                    if (c0 + 2 < K) av.z = A[(size_t)ar * lda + c0 + 2];
                    if (c0 + 3 < K) av.w = A[(size_t)ar * lda + c0 + 3];
                }
            }
            bv = make_float4(0.f, 0.f, 0.f, 0.f);
            int br = k + brow, bc = n0 + bcol;
            if (br < K) {
                if (bc + 3 < N) bv = *(const float4*)(B + (size_t)br * ldb + bc);
                else {
                    if (bc + 0 < N) bv.x = B[(size_t)br * ldb + bc + 0];
                    if (bc + 1 < N) bv.y = B[(size_t)br * ldb + bc + 1];
                    if (bc + 2 < N) bv.z = B[(size_t)br * ldb + bc + 2];
                    if (bc + 3 < N) bv.w = B[(size_t)br * ldb + bc + 3];
                }
            }
        }
#pragma unroll
        for (int kk = 0; kk < 8; kk++) {
            float4 a0 = *(const float4*)&As[cur][kk][ty * 8];
            float4 a1 = *(const float4*)&As[cur][kk][ty * 8 + 4];
            const ull* bp = (const ull*)&Bs[cur][kk][tx * 8];
            ull b01 = bp[0], b23 = bp[1], b45 = bp[2], b67 = bp[3];
            float a[8] = {a0.x, a0.y, a0.z, a0.w, a1.x, a1.y, a1.z, a1.w};
#pragma unroll
            for (int i = 0; i < 8; i++) {
                ull ai = pack2(a[i], a[i]);
                acc2[i][0] = fma2(ai, b01, acc2[i][0]);
                acc2[i][1] = fma2(ai, b23, acc2[i][1]);
                acc2[i][2] = fma2(ai, b45, acc2[i][2]);
                acc2[i][3] = fma2(ai, b67, acc2[i][3]);
            }
        }
        if (hasNext) {
            __syncthreads();
            As[nxt][acol + 0][arow] = av.x;
            As[nxt][acol + 1][arow] = av.y;
            As[nxt][acol + 2][arow] = av.z;
            As[nxt][acol + 3][arow] = av.w;
            *(float4*)&Bs[nxt][brow][bcol] = bv;
            __syncthreads();
        }
    }
#pragma unroll
    for (int i = 0; i < 8; i++) {
        int row = m0 + ty * 8 + i;
        if (row >= M) continue;
        float* Cr = C + (size_t)row * ldc;
        int col0 = n0 + tx * 8;
        float acc[8];
#pragma unroll
        for (int j = 0; j < 4; j++) unpack2(acc2[i][j], acc[j * 2], acc[j * 2 + 1]);
        if (col0 + 7 < N) {
            *(float4*)(Cr + col0) = make_float4(acc[0], acc[1], acc[2], acc[3]);
            *(float4*)(Cr + col0 + 4) = make_float4(acc[4], acc[5], acc[6], acc[7]);
        } else {
#pragma unroll
            for (int j = 0; j < 8; j++)
                if (col0 + j < N) Cr[col0 + j] = acc[j];
        }
    }
}

// ---------------- gc 1x1 + residual + BN partial stats (f32x2) ----------------
__global__ void k_gcres(const float* __restrict__ XG, const float* __restrict__ Y,
                        const float* __restrict__ Xc, float* __restrict__ Xn,
                        const float* __restrict__ gcw, const float* __restrict__ gcb,
                        float* __restrict__ part, int Tin, int Tout, int dd) {
    __shared__ __align__(16) float swg[160 * 32];
    __shared__ float sgb[32];
    __shared__ float sredS[4][32];
    __shared__ float sredQ[4][32];
    int tid = threadIdx.x;
    for (int idx = tid; idx < 160 * 32; idx += 128) {
        int c = idx / 32, o = idx % 32;
        swg[idx] = gcw[o * 160 + c];
    }
    if (tid < 32) sgb[tid] = gcb[tid];
    __syncthreads();
    int n = blockIdx.x * 128 + tid;
    int t = blockIdx.y, b = blockIdx.z;
    bool active = (n < NNODE);
    ull acc2[16];
#pragma unroll
    for (int q = 0; q < 16; q++)
        acc2[q] = active ? pack2(sgb[q * 2], sgb[q * 2 + 1]) : pack2(0.f, 0.f);
    if (active) {
        for (int c = 0; c < 32; c++) {
            float val = XG[((size_t)(b * 32 + c) * Tout + t) * NNODE + n];
            ull vd = pack2(val, val);
            const ull* w2 = (const ull*)&swg[c * 32];
#pragma unroll
            for (int q = 0; q < 16; q++) acc2[q] = fma2(vd, w2[q], acc2[q]);
        }
        for (int e = 0; e < 4; e++) {
            for (int c = 0; c < 32; c++) {
                size_t m = (size_t)(b * 32 + c) * Tout + t;
                float val = Y[m * 2000 + e * 500 + n];
                ull vd = pack2(val, val);
                const ull* w2 = (const ull*)&swg[(32 + e * 32 + c) * 32];
#pragma unroll
                for (int q = 0; q < 16; q++) acc2[q] = fma2(vd, w2[q], acc2[q]);
            }
        }
    }
    float acc[32];
#pragma unroll
    for (int q = 0; q < 16; q++) unpack2(acc2[q], acc[q * 2], acc[q * 2 + 1]);
    if (active) {
#pragma unroll
        for (int o = 0; o < 32; o++) {
            acc[o] += Xc[((size_t)(b * 32 + o) * Tin + t + dd) * NNODE + n];
            Xn[((size_t)(b * 32 + o) * Tout + t) * NNODE + n] = acc[o];
        }
    }
    int lane = tid & 31, warp = tid >> 5;
#pragma unroll
    for (int o = 0; o < 32; o++) {
        float s = active ? acc[o] : 0.f;
        float q = s * s;
#pragma unroll
        for (int off = 16; off; off >>= 1) {
            s += __shfl_down_sync(0xffffffffu, s, off);
            q += __shfl_down_sync(0xffffffffu, q, off);
        }
        if (lane == 0) { sredS[warp][o] = s; sredQ[warp][o] = q; }
    }
    __syncthreads();
    if (tid < 64) {
        int o = tid & 31;
        bool isq = (tid >= 32);
        float v = 0.f;
#pragma unroll
        for (int w = 0; w < 4; w++) v += (isq ? sredQ[w][o] : sredS[w][o]);
        size_t bidx = (size_t)(blockIdx.z * gridDim.y + blockIdx.y) * gridDim.x + blockIdx.x;
        part[bidx * 64 + tid] = v;
    }
}

// reduce partials -> fused BN scale/shift
__global__ void k_redstats(const float* __restrict__ part, int nblk, float cnt,
                           const float* __restrict__ g, const float* __restrict__ bta,
                           float* __restrict__ ab) {
    int c = blockIdx.x;
    int tid = threadIdx.x;
    double s = 0.0, q = 0.0;
    for (int i = tid; i < nblk; i += 256) {
        s += (double)part[(size_t)i * 64 + c];
        q += (double)part[(size_t)i * 64 + 32 + c];
    }
    __shared__ double rs[256], rq[256];
    rs[tid] = s; rq[tid] = q;
    __syncthreads();
    for (int st = 128; st > 0; st >>= 1) {
        if (tid < st) { rs[tid] += rs[tid + st]; rq[tid] += rq[tid + st]; }
        __syncthreads();
    }
    if (tid == 0) {
        float mean = (float)(rs[0] / cnt);
        float var = (float)(rq[0] / cnt) - mean * mean;
        float a = g[c] * rsqrtf(var + BN_EPS);
        ab[c] = a;
        ab[32 + c] = bta[c] - mean * a;
    }
}

__global__ void k_bnnorm(float* __restrict__ X, const float* __restrict__ ab, int Tout) {
    int idx = blockIdx.x * 256 + threadIdx.x;
    int total = BB * 32 * Tout * NNODE;
    if (idx >= total) return;
    int c = (idx / (Tout * NNODE)) % 32;
    X[idx] = X[idx] * ab[c] + ab[32 + c];
}

// ---------------- output head ----------------
__global__ void k_transpose_skip(const float* __restrict__ skip, float* __restrict__ Srelu) {
    __shared__ float tile[32][33];
    int b = blockIdx.z;
    int n0 = blockIdx.x * 32, c0 = blockIdx.y * 32;
    int n = n0 + threadIdx.x, c = c0 + threadIdx.y;
    tile[threadIdx.y][threadIdx.x] = (n < NNODE) ? skip[(size_t)(b * NSKIPC + c) * NNODE + n] : 0.f;
    __syncthreads();
    int n2 = n0 + threadIdx.y, c2 = c0 + threadIdx.x;
    if (n2 < NNODE)
        Srelu[(size_t)(b * NNODE + n2) * NSKIPC + c2] = fmaxf(tile[threadIdx.x][threadIdx.y], 0.f);
}

__global__ void k_transpose_o1w(const float* __restrict__ o1w, float* __restrict__ o1wT) {
    int idx = blockIdx.x * 256 + threadIdx.x;
    if (idx >= NENDC * NSKIPC) return;
    int h = idx / NSKIPC, c = idx % NSKIPC;
    o1wT[c * NENDC + h] = o1w[idx];
}

__global__ void k_headfinal(const float* __restrict__ H, const float* __restrict__ o1b,
                            const float* __restrict__ o2w, const float* __restrict__ o2b,
                            float* __restrict__ out) {
    int warp = threadIdx.x >> 5, lane = threadIdx.x & 31;
    int row = blockIdx.x * 4 + warp;
    if (row >= BB * NNODE) return;
    int b = row / NNODE, n = row % NNODE;
    const float* Hr = H + (size_t)row * NENDC;
    float h[16];
#pragma unroll
    for (int i = 0; i < 16; i++)
        h[i] = fmaxf(Hr[lane + i * 32] + o1b[lane + i * 32], 0.f);
#pragma unroll
    for (int p = 0; p < NPREDC; p++) {
        float acc = 0.f;
#pragma unroll
        for (int i = 0; i < 16; i++) acc += o2w[p * NENDC + lane + i * 32] * h[i];
#pragma unroll
        for (int off = 16; off; off >>= 1) acc += __shfl_down_sync(0xffffffffu, acc, off);
        if (lane == 0) out[(size_t)(b * NPREDC + p) * NNODE + n] = acc + o2b[p];
    }
}

// ---------------- host launcher ----------------
extern "C" void kernel_launch(void* const* d_in, const int* in_sizes, int n_in,
                              void* d_out, int out_size) {
    const float* inputs = (const float*)d_in[0];
    const float* factor = (const float*)d_in[1];
    const float* map_w  = (const float*)d_in[2];
    const float* map_b  = (const float*)d_in[3];
    const float* a1w    = (const float*)d_in[4];
    const float* a1b    = (const float*)d_in[5];
    const float* a2w    = (const float*)d_in[6];
    const float* a2b    = (const float*)d_in[7];
    const float* a3w    = (const float*)d_in[8];
    const float* a3b    = (const float*)d_in[9];
    const float* enter_w = (const float*)d_in[10];
    const float* enter_b = (const float*)d_in[11];
    const float* filt_w = (const float*)d_in[12];
    const float* filt_b = (const float*)d_in[13];
    const float* gate_w = (const float*)d_in[14];
    const float* gate_b = (const float*)d_in[15];
    const float* skp_w  = (const float*)d_in[16];
    const float* skp_b  = (const float*)d_in[17];
    const float* gc_w   = (const float*)d_in[18];
    const float* gc_b   = (const float*)d_in[19];
    const float* bn_g   = (const float*)d_in[20];
    const float* bn_b   = (const float*)d_in[21];
    const float* o1w    = (const float*)d_in[22];
    const float* o1b    = (const float*)d_in[23];
    const float* o2w    = (const float*)d_in[24];
    const float* o2b    = (const float*)d_in[25];

    float *pScat, *pY, *pX0, *pX1, *pXG, *pSkip, *pSrelu, *pO1T, *pPart, *pAB;
    cudaGetSymbolAddress((void**)&pScat, g_Scat);
    cudaGetSymbolAddress((void**)&pY, g_Y);
    cudaGetSymbolAddress((void**)&pX0, g_X0);
    cudaGetSymbolAddress((void**)&pX1, g_X1);
    cudaGetSymbolAddress((void**)&pXG, g_XG);
    cudaGetSymbolAddress((void**)&pSkip, g_skip);
    cudaGetSymbolAddress((void**)&pSrelu, g_Srelu);
    cudaGetSymbolAddress((void**)&pO1T, g_o1wT);
    cudaGetSymbolAddress((void**)&pPart, g_part);
    cudaGetSymbolAddress((void**)&pAB, g_bnab);

    float* out = (float*)d_out;
    const int ySize = BB * NPREDC * NNODE;
    const int supSize = 2 * NNODE * NNODE;
    int writeSup = (out_size >= ySize + supSize) ? 1 : 0;
    float* outSup = out + ySize;

    // adaptive adjacency
    k_v<<<NNODE, 32>>>(factor, map_w, map_b);
    k_pq<<<NNODE, 64>>>(a1w, a1b);
    k_adjmlp<<<NNODE, 128>>>(a2w, a2b, a3w, a3b);
    k_softmax<<<2 * NNODE, 256>>>(outSup, writeSup);
    // A^2 for both supports in one batched launch
    sgemm<<<dim3(4, 4, 2), 256>>>(pScat, pScat, pScat + 500, 500, 500, 500, 2000, 2000, 2000,
                                  1000, 1000, 1000);
    // input split + enter conv
    k_tmp<<<dim3(TT, BB), 64>>>(inputs, factor);
    k_enter<<<dim3(4, RFh, BB), 128>>>(inputs, factor, enter_w, enter_b, pX0);

    static const int Tin[LL] = {13, 12, 10, 9, 7, 6, 4, 3};
    static const int Dd[LL]  = {1, 2, 1, 2, 1, 2, 1, 2};
    static const int To[LL]  = {12, 10, 9, 7, 6, 4, 3, 1};
    float* Xc = pX0;
    float* Xn = pX1;
    for (int i = 0; i < LL; i++) {
        k_gatefilter<<<dim3(4, To[i], BB), 128>>>(Xc, pXG,
            filt_w + i * 2048, filt_b + i * 32, gate_w + i * 2048, gate_b + i * 32,
            Tin[i], To[i], Dd[i]);
        k_skip<<<dim3(63, BB), 256>>>(pXG, pSkip, skp_w + i * 8192, skp_b + i * 256,
                                      To[i], (i == 0) ? 1 : 0);
        if (i < LL - 1) {   // layer 8's graph_conv/BN output is dead code
            int M = BB * 32 * To[i];
            sgemm<<<dim3(16, (M + 127) / 128), 256>>>(pXG, pScat, pY, M, 2000, 500,
                                                      500, 2000, 2000, 0, 0, 0);
            int nblk = 4 * To[i] * BB;
            k_gcres<<<dim3(4, To[i], BB), 128>>>(pXG, pY, Xc, Xn,
                gc_w + i * 5120, gc_b + i * 32, pPart, Tin[i], To[i], Dd[i]);
            k_redstats<<<32, 256>>>(pPart, nblk, (float)(BB * To[i] * NNODE),
                                    bn_g + i * 32, bn_b + i * 32, pAB);
            int tot = BB * 32 * To[i] * NNODE;
            k_bnnorm<<<(tot + 255) / 256, 256>>>(Xn, pAB, To[i]);
            float* t = Xc; Xc = Xn; Xn = t;
        }
    }
    // output head
    k_transpose_skip<<<dim3(16, 8, BB), dim3(32, 32)>>>(pSkip, pSrelu);
    k_transpose_o1w<<<(NENDC * NSKIPC + 255) / 256, 256>>>(o1w, pO1T);
    sgemm<<<dim3(4, 125), 256>>>(pSrelu, pO1T, pY, BB * NNODE, NENDC, NSKIPC,
                                 NSKIPC, NENDC, NENDC, 0, 0, 0);
    k_headfinal<<<(BB * NNODE + 3) / 4, 128>>>(pY, o1b, o2w, o2b, out);
}

// round 4
// speedup vs baseline: 1.7562x; 1.5383x over previous
#include <cuda_runtime.h>
#include <math.h>
#include <stdint.h>

// ---------------- static problem config ----------------
#define BB 32
#define TT 12
#define NNODE 500
#define NSKIPC 256
#define NENDC 512
#define NPREDC 12
#define LL 8
#define RFh 13
#define BN_EPS 1e-5f

typedef unsigned long long ull;
typedef unsigned int u32;

__device__ __forceinline__ ull pack2(float lo, float hi) {
    ull r; asm("mov.b64 %0,{%1,%2};" : "=l"(r) : "f"(lo), "f"(hi)); return r;
}
__device__ __forceinline__ ull fma2(ull a, ull b, ull c) {
    ull d; asm("fma.rn.f32x2 %0,%1,%2,%3;" : "=l"(d) : "l"(a), "l"(b), "l"(c)); return d;
}
__device__ __forceinline__ void unpack2(ull v, float& lo, float& hi) {
    asm("mov.b64 {%0,%1},%2;" : "=f"(lo), "=f"(hi) : "l"(v));
}
__device__ __forceinline__ float to_tf32(float x) {
    u32 r; asm("cvt.rna.tf32.f32 %0, %1;" : "=r"(r) : "f"(x));
    return __uint_as_float(r);
}
__device__ __forceinline__ void mma_tf32(float* c, const u32* a, const u32* b) {
    asm("mma.sync.aligned.m16n8k8.row.col.f32.tf32.tf32.f32 "
        "{%0,%1,%2,%3},{%4,%5,%6,%7},{%8,%9},{%0,%1,%2,%3};"
        : "+f"(c[0]), "+f"(c[1]), "+f"(c[2]), "+f"(c[3])
        : "r"(a[0]), "r"(a[1]), "r"(a[2]), "r"(a[3]), "r"(b[0]), "r"(b[1]));
}

// ---------------- device scratch ----------------
__device__ float g_P[NNODE * 64];
__device__ float g_Q[NNODE * 64];
__device__ float g_eraw[2 * NNODE * NNODE];
__device__ float g_Scat[NNODE * 2000];            // [v][ A0 | A0^2 | A1 | A1^2 ]
__device__ float g_tmp[BB * TT * 32 * 2];
__device__ float g_X0[BB * 32 * RFh * NNODE];
__device__ float g_X1[BB * 32 * RFh * NNODE];
__device__ float g_XG[BB * 32 * 12 * NNODE];
__device__ float g_Y[12288 * 2000];               // diffusion outputs; reused as head hidden H
__device__ float g_skip[BB * NSKIPC * NNODE];
__device__ float g_Srelu[BB * NNODE * NSKIPC];
__device__ float g_o1wT[NSKIPC * NENDC];
__device__ float g_part[1536 * 64];               // per-block BN partial sums
__device__ float g_bnab[64];                      // fused BN scale/shift

// ---------------- adjacency ----------------
// fused: v = relu(factor@map_w+map_b); P = v@a1w_top; Q = a1b + v@a1w_bot
__global__ void k_pq(const float* __restrict__ factor, const float* __restrict__ map_w,
                     const float* __restrict__ map_b,
                     const float* __restrict__ a1w, const float* __restrict__ a1b) {
    __shared__ float vv[32];
    int j = blockIdx.x, h = threadIdx.x;   // 64 threads
    if (h < 32) {
        float acc = map_b[h];
#pragma unroll
        for (int u = 0; u < 32; u++) acc += factor[j * 32 + u] * map_w[u * 32 + h];
        vv[h] = fmaxf(acc, 0.f);
    }
    __syncthreads();
    float p = 0.f, q = a1b[h];
#pragma unroll
    for (int d = 0; d < 32; d++) {
        p += vv[d] * a1w[d * 64 + h];
        q += vv[d] * a1w[(32 + d) * 64 + h];
    }
    g_P[j * 64 + h] = p;
    g_Q[j * 64 + h] = q;
}

__global__ void k_adjmlp(const float* __restrict__ a2w, const float* __restrict__ a2b,
                         const float* __restrict__ a3w, const float* __restrict__ a3b) {
    __shared__ float Pt[128][65];
    __shared__ __align__(16) float sA2[64][32];
    __shared__ float sQ[64];
    __shared__ float sA3[64];
    __shared__ float sA2b[32];
    __shared__ float sA3b[2];
    int i = blockIdx.x, tid = threadIdx.x;
    for (int k = tid; k < 64 * 32; k += 128) sA2[k / 32][k % 32] = a2w[k];
    if (tid < 64) { sQ[tid] = g_Q[i * 64 + tid]; sA3[tid] = a3w[tid]; }
    if (tid < 32) sA2b[tid] = a2b[tid];
    if (tid < 2) sA3b[tid] = a3b[tid];
    for (int j0 = 0; j0 < NNODE; j0 += 128) {
        __syncthreads();
        int cnt = min(128, NNODE - j0);
        for (int k = tid; k < cnt * 64; k += 128)
            Pt[k / 64][k % 64] = g_P[(j0 + (k / 64)) * 64 + (k % 64)];
        __syncthreads();
        if (tid < cnt) {
            int j = j0 + tid;
            float h1[64];
#pragma unroll
            for (int h = 0; h < 64; h++) h1[h] = fmaxf(Pt[tid][h] + sQ[h], 0.f);
            float e0 = sA3b[0], e1 = sA3b[1];
#pragma unroll
            for (int c = 0; c < 32; c++) {
                float acc = sA2b[c];
#pragma unroll
                for (int h = 0; h < 64; h++) acc += h1[h] * sA2[h][c];
                acc = fmaxf(acc, 0.f);
                e0 += acc * sA3[c * 2];
                e1 += acc * sA3[c * 2 + 1];
            }
            g_eraw[i * NNODE + j] = e0;
            g_eraw[NNODE * NNODE + i * NNODE + j] = e1;
        }
    }
}

__global__ void k_softmax(float* __restrict__ outSup, int writeSup) {
    int bid = blockIdx.x;
    int e = bid / NNODE, i = bid % NNODE;
    const float* row = g_eraw + e * NNODE * NNODE + i * NNODE;
    __shared__ float red[256];
    int tid = threadIdx.x;
    float m = -1e30f;
    for (int j = tid; j < NNODE; j += 256) m = fmaxf(m, row[j]);
    red[tid] = m; __syncthreads();
    for (int s = 128; s > 0; s >>= 1) { if (tid < s) red[tid] = fmaxf(red[tid], red[tid + s]); __syncthreads(); }
    m = red[0]; __syncthreads();
    float sum = 0.f;
    for (int j = tid; j < NNODE; j += 256) sum += expf(row[j] - m);
    red[tid] = sum; __syncthreads();
    for (int s = 128; s > 0; s >>= 1) { if (tid < s) red[tid] += red[tid + s]; __syncthreads(); }
    float inv = 1.f / red[0];
    for (int j = tid; j < NNODE; j += 256) {
        float p = expf(row[j] - m) * inv;
        if (j == i) p = fmaxf(p, 1.f);
        g_Scat[i * 2000 + e * 1000 + j] = p;
        if (writeSup) outSup[(e * NNODE + i) * NNODE + j] = p;
    }
}

// ---------------- tf32 tensor-core GEMM: 128x128 tile, KC=16, double-buffered ----------------
// C[M,N] = A[M,K] @ B[K,N]  (row-major, leading dims; batch via blockIdx.z strides)
__global__ __launch_bounds__(256)
void tgemm(const float* __restrict__ A, const float* __restrict__ B, float* __restrict__ C,
           int M, int N, int K, int lda, int ldb, int ldc,
           int sA, int sB, int sC) {
    __shared__ __align__(16) float As[2][16][136];   // [buf][k][m]
    __shared__ __align__(16) float Bs[2][16][136];   // [buf][k][n]
    A += (size_t)blockIdx.z * sA;
    B += (size_t)blockIdx.z * sB;
    C += (size_t)blockIdx.z * sC;
    int tid = threadIdx.x;
    int m0 = blockIdx.y * 128, n0 = blockIdx.x * 128;
    int lane = tid & 31, wid = tid >> 5;
    int wm = wid & 1, wn = wid >> 1;          // warp grid 2(m) x 4(n); warp tile 64x32
    int gid = lane >> 2, tig = lane & 3;

    // loader indices
    int lm = tid >> 1, lrh = tid & 1;         // A: row lm, k-half lrh (8 cols)
    int lkl = tid >> 4, lnq = (tid & 15) << 3;// B: k row lkl, 8 cols at lnq

    float acc[4][4][4];
#pragma unroll
    for (int mi = 0; mi < 4; mi++)
#pragma unroll
        for (int ni = 0; ni < 4; ni++)
#pragma unroll
            for (int r = 0; r < 4; r++) acc[mi][ni][r] = 0.f;

    int nkt = (K + 15) / 16;

    // ---- prologue: stage chunk 0 into buf 0 ----
    {
        int kc0 = 0;
        // A
        float av[8];
        int row = m0 + lm, c0 = kc0 + lrh * 8;
        if (row < M && c0 + 7 < K) {
            float4 p = *(const float4*)(A + (size_t)row * lda + c0);
            float4 q = *(const float4*)(A + (size_t)row * lda + c0 + 4);
            av[0]=p.x; av[1]=p.y; av[2]=p.z; av[3]=p.w; av[4]=q.x; av[5]=q.y; av[6]=q.z; av[7]=q.w;
        } else {
#pragma unroll
            for (int l = 0; l < 8; l++)
                av[l] = (row < M && c0 + l < K) ? A[(size_t)row * lda + c0 + l] : 0.f;
        }
#pragma unroll
        for (int l = 0; l < 8; l++) As[0][lrh * 8 + l][lm] = to_tf32(av[l]);
        // B
        float bv[8];
        int br = kc0 + lkl, bc = n0 + lnq;
        if (br < K && bc + 7 < N) {
            float4 p = *(const float4*)(B + (size_t)br * ldb + bc);
            float4 q = *(const float4*)(B + (size_t)br * ldb + bc + 4);
            bv[0]=p.x; bv[1]=p.y; bv[2]=p.z; bv[3]=p.w; bv[4]=q.x; bv[5]=q.y; bv[6]=q.z; bv[7]=q.w;
        } else {
#pragma unroll
            for (int l = 0; l < 8; l++)
                bv[l] = (br < K && bc + l < N) ? B[(size_t)br * ldb + bc + l] : 0.f;
        }
        float4 f0 = make_float4(to_tf32(bv[0]), to_tf32(bv[1]), to_tf32(bv[2]), to_tf32(bv[3]));
        float4 f1 = make_float4(to_tf32(bv[4]), to_tf32(bv[5]), to_tf32(bv[6]), to_tf32(bv[7]));
        *(float4*)&Bs[0][lkl][lnq] = f0;
        *(float4*)&Bs[0][lkl][lnq + 4] = f1;
    }
    __syncthreads();

    for (int kt = 0; kt < nkt; kt++) {
        int cur = kt & 1;
        bool hn = (kt + 1 < nkt);
        float av[8], bv[8];
        if (hn) {
            int kc0 = (kt + 1) * 16;
            int row = m0 + lm, c0 = kc0 + lrh * 8;
            if (row < M && c0 + 7 < K) {
                float4 p = *(const float4*)(A + (size_t)row * lda + c0);
                float4 q = *(const float4*)(A + (size_t)row * lda + c0 + 4);
                av[0]=p.x; av[1]=p.y; av[2]=p.z; av[3]=p.w; av[4]=q.x; av[5]=q.y; av[6]=q.z; av[7]=q.w;
            } else {
#pragma unroll
                for (int l = 0; l < 8; l++)
                    av[l] = (row < M && c0 + l < K) ? A[(size_t)row * lda + c0 + l] : 0.f;
            }
            int br = kc0 + lkl, bc = n0 + lnq;
            if (br < K && bc + 7 < N) {
                float4 p = *(const float4*)(B + (size_t)br * ldb + bc);
                float4 q = *(const float4*)(B + (size_t)br * ldb + bc + 4);
                bv[0]=p.x; bv[1]=p.y; bv[2]=p.z; bv[3]=p.w; bv[4]=q.x; bv[5]=q.y; bv[6]=q.z; bv[7]=q.w;
            } else {
#pragma unroll
                for (int l = 0; l < 8; l++)
                    bv[l] = (br < K && bc + l < N) ? B[(size_t)br * ldb + bc + l] : 0.f;
            }
        }
        // compute on cur
#pragma unroll
        for (int ks = 0; ks < 16; ks += 8) {
            u32 af[4][4];
            u32 bf[4][2];
#pragma unroll
            for (int mi = 0; mi < 4; mi++) {
                int mb = wm * 64 + mi * 16 + gid;
                af[mi][0] = __float_as_uint(As[cur][ks + tig][mb]);
                af[mi][1] = __float_as_uint(As[cur][ks + tig][mb + 8]);
                af[mi][2] = __float_as_uint(As[cur][ks + tig + 4][mb]);
                af[mi][3] = __float_as_uint(As[cur][ks + tig + 4][mb + 8]);
            }
#pragma unroll
            for (int ni = 0; ni < 4; ni++) {
                int nb = wn * 32 + ni * 8 + gid;
                bf[ni][0] = __float_as_uint(Bs[cur][ks + tig][nb]);
                bf[ni][1] = __float_as_uint(Bs[cur][ks + tig + 4][nb]);
            }
#pragma unroll
            for (int mi = 0; mi < 4; mi++)
#pragma unroll
                for (int ni = 0; ni < 4; ni++)
                    mma_tf32(acc[mi][ni], af[mi], bf[ni]);
        }
        if (hn) {
            int nxt = cur ^ 1;
#pragma unroll
            for (int l = 0; l < 8; l++) As[nxt][lrh * 8 + l][lm] = to_tf32(av[l]);
            float4 f0 = make_float4(to_tf32(bv[0]), to_tf32(bv[1]), to_tf32(bv[2]), to_tf32(bv[3]));
            float4 f1 = make_float4(to_tf32(bv[4]), to_tf32(bv[5]), to_tf32(bv[6]), to_tf32(bv[7]));
            *(float4*)&Bs[nxt][lkl][lnq] = f0;
            *(float4*)&Bs[nxt][lkl][lnq + 4] = f1;
            __syncthreads();
        }
    }

    // ---- epilogue ----
#pragma unroll
    for (int mi = 0; mi < 4; mi++) {
        int r0 = m0 + wm * 64 + mi * 16 + gid;
        int r1 = r0 + 8;
#pragma unroll
        for (int ni = 0; ni < 4; ni++) {
            int cc = n0 + wn * 32 + ni * 8 + tig * 2;
            if (r0 < M) {
                if (cc + 1 < N) *(float2*)(C + (size_t)r0 * ldc + cc) = make_float2(acc[mi][ni][0], acc[mi][ni][1]);
                else if (cc < N) C[(size_t)r0 * ldc + cc] = acc[mi][ni][0];
            }
            if (r1 < M) {
                if (cc + 1 < N) *(float2*)(C + (size_t)r1 * ldc + cc) = make_float2(acc[mi][ni][2], acc[mi][ni][3]);
                else if (cc < N) C[(size_t)r1 * ldc + cc] = acc[mi][ni][2];
            }
        }
    }
}

// ---------------- input split + enter ----------------
__global__ void k_tmp(const float* __restrict__ inputs, const float* __restrict__ factor) {
    int t = blockIdx.x, b = blockIdx.y, tid = threadIdx.x;
    int u = tid / 2, f = tid % 2;
    const float* inp = inputs + ((size_t)(b * TT + t) * NNODE) * 2 + f;
    float acc = 0.f;
    for (int n = 0; n < NNODE; n++) acc += inp[n * 2] * factor[n * 32 + u];
    g_tmp[(b * TT + t) * 64 + tid] = acc;
}

__global__ void k_enter(const float* __restrict__ inputs, const float* __restrict__ factor,
                        const float* __restrict__ ew, const float* __restrict__ eb,
                        float* __restrict__ X0) {
    __shared__ float sw[128], sb[32], stmp[64];
    int b = blockIdx.z, tp = blockIdx.y;
    int tid = threadIdx.x;
    if (tid < 128) sw[tid] = ew[tid];
    if (tid < 32) sb[tid] = eb[tid];
    if (tp > 0 && tid < 64) stmp[tid] = g_tmp[(b * TT + (tp - 1)) * 64 + tid];
    __syncthreads();
    int n = blockIdx.x * 128 + tid;
    if (n >= NNODE) return;
    if (tp == 0) {
#pragma unroll
        for (int o = 0; o < 32; o++)
            X0[((size_t)(b * 32 + o) * RFh + 0) * NNODE + n] = sb[o];
    } else {
        int t = tp - 1;
        float s0 = 0.f, s1 = 0.f;
#pragma unroll
        for (int u = 0; u < 32; u++) {
            float fv = factor[n * 32 + u];
            s0 += fv * stmp[u * 2];
            s1 += fv * stmp[u * 2 + 1];
        }
        float i0 = inputs[((size_t)(b * TT + t) * NNODE + n) * 2 + 0];
        float i1 = inputs[((size_t)(b * TT + t) * NNODE + n) * 2 + 1];
        float r0 = i0 - s0, r1 = i1 - s1;
#pragma unroll
        for (int o = 0; o < 32; o++) {
            float v = sb[o] + sw[o * 4] * s0 + sw[o * 4 + 1] * s1 + sw[o * 4 + 2] * r0 + sw[o * 4 + 3] * r1;
            X0[((size_t)(b * 32 + o) * RFh + tp) * NNODE + n] = v;
        }
    }
}

// ---------------- gated dilated temporal conv (f32x2) ----------------
__global__ void k_gatefilter(const float* __restrict__ X, float* __restrict__ XG,
                             const float* __restrict__ fw, const float* __restrict__ fb,
                             const float* __restrict__ gw, const float* __restrict__ gb,
                             int Tin, int Tout, int dd) {
    __shared__ __align__(16) float swf[2048];
    __shared__ __align__(16) float swg[2048];
    __shared__ float sfb[32], sgb[32];
    int tid = threadIdx.x;
    for (int idx = tid; idx < 2048; idx += 128) {
        int c = idx >> 6, r = idx & 63, kk = r >> 5, o = r & 31;
        swf[idx] = fw[(o << 6) + (c << 1) + kk];
        swg[idx] = gw[(o << 6) + (c << 1) + kk];
    }
    if (tid < 32) { sfb[tid] = fb[tid]; sgb[tid] = gb[tid]; }
    __syncthreads();
    int n = blockIdx.x * 128 + tid;
    if (n >= NNODE) return;
    int t = blockIdx.y, b = blockIdx.z;
    ull fa2[16], ga2[16];
#pragma unroll
    for (int p = 0; p < 16; p++) {
        fa2[p] = pack2(sfb[p * 2], sfb[p * 2 + 1]);
        ga2[p] = pack2(sgb[p * 2], sgb[p * 2 + 1]);
    }
    const float* Xb = X + (size_t)(b * 32) * Tin * NNODE + n;
    for (int c = 0; c < 32; c++) {
        float xa = Xb[(size_t)(c * Tin + t) * NNODE];
        float xb = Xb[(size_t)(c * Tin + t + dd) * NNODE];
        ull xad = pack2(xa, xa), xbd = pack2(xb, xb);
        const ull* wf0 = (const ull*)&swf[c * 64];
        const ull* wf1 = (const ull*)&swf[c * 64 + 32];
        const ull* wg0 = (const ull*)&swg[c * 64];
        const ull* wg1 = (const ull*)&swg[c * 64 + 32];
#pragma unroll
        for (int p = 0; p < 16; p++) {
            fa2[p] = fma2(xad, wf0[p], fa2[p]);
            fa2[p] = fma2(xbd, wf1[p], fa2[p]);
            ga2[p] = fma2(xad, wg0[p], ga2[p]);
            ga2[p] = fma2(xbd, wg1[p], ga2[p]);
        }
    }
#pragma unroll
    for (int p = 0; p < 16; p++) {
        float f0, f1, g0, g1;
        unpack2(fa2[p], f0, f1);
        unpack2(ga2[p], g0, g1);
        float s0 = 1.f / (1.f + expf(-g0));
        float s1 = 1.f / (1.f + expf(-g1));
        XG[((size_t)(b * 32 + p * 2 + 0) * Tout + t) * NNODE + n] = tanhf(f0) * s0;
        XG[((size_t)(b * 32 + p * 2 + 1) * Tout + t) * NNODE + n] = tanhf(f1) * s1;
    }
}

// ---------------- skip (last timestep only) ----------------
__global__ void k_skip(const float* __restrict__ XG, float* __restrict__ skip,
                       const float* __restrict__ sw_g, const float* __restrict__ sb_g,
                       int Tout, int first) {
    __shared__ float xs[8][32];
    int b = blockIdx.y;
    int n0 = blockIdx.x * 8;
    int tid = threadIdx.x;
    {
        int nn = tid / 32, c = tid % 32;
        int n = n0 + nn;
        xs[nn][c] = (n < NNODE) ? XG[((size_t)(b * 32 + c) * Tout + (Tout - 1)) * NNODE + n] : 0.f;
    }
    __syncthreads();
    int o = tid;
    float w[32];
#pragma unroll
    for (int c = 0; c < 32; c++) w[c] = sw_g[o * 32 + c];
    float bias = sb_g[o];
#pragma unroll
    for (int nn = 0; nn < 8; nn++) {
        int n = n0 + nn;
        if (n >= NNODE) break;
        float acc = bias;
#pragma unroll
        for (int c = 0; c < 32; c++) acc += w[c] * xs[nn][c];
        size_t idx = (size_t)(b * NSKIPC + o) * NNODE + n;
        if (first) skip[idx] = acc;
        else skip[idx] += acc;
    }
}

// ---------------- gc 1x1 + residual + BN partial stats (f32x2) ----------------
__global__ void k_gcres(const float* __restrict__ XG, const float* __restrict__ Y,
                        const float* __restrict__ Xc, float* __restrict__ Xn,
                        const float* __restrict__ gcw, const float* __restrict__ gcb,
                        float* __restrict__ part, int Tin, int Tout, int dd) {
    __shared__ __align__(16) float swg[160 * 32];
    __shared__ float sgb[32];
    __shared__ float sredS[4][32];
    __shared__ float sredQ[4][32];
    int tid = threadIdx.x;
    for (int idx = tid; idx < 160 * 32; idx += 128) {
        int c = idx / 32, o = idx % 32;
        swg[idx] = gcw[o * 160 + c];
    }
    if (tid < 32) sgb[tid] = gcb[tid];
    __syncthreads();
    int n = blockIdx.x * 128 + tid;
    int t = blockIdx.y, b = blockIdx.z;
    bool active = (n < NNODE);
    ull acc2[16];
#pragma unroll
    for (int q = 0; q < 16; q++)
        acc2[q] = active ? pack2(sgb[q * 2], sgb[q * 2 + 1]) : pack2(0.f, 0.f);
    if (active) {
        for (int c = 0; c < 32; c++) {
            float val = XG[((size_t)(b * 32 + c) * Tout + t) * NNODE + n];
            ull vd = pack2(val, val);
            const ull* w2 = (const ull*)&swg[c * 32];
#pragma unroll
            for (int q = 0; q < 16; q++) acc2[q] = fma2(vd, w2[q], acc2[q]);
        }
        for (int e = 0; e < 4; e++) {
            for (int c = 0; c < 32; c++) {
                size_t m = (size_t)(b * 32 + c) * Tout + t;
                float val = Y[m * 2000 + e * 500 + n];
                ull vd = pack2(val, val);
                const ull* w2 = (const ull*)&swg[(32 + e * 32 + c) * 32];
#pragma unroll
                for (int q = 0; q < 16; q++) acc2[q] = fma2(vd, w2[q], acc2[q]);
            }
        }
    }
    float acc[32];
#pragma unroll
    for (int q = 0; q < 16; q++) unpack2(acc2[q], acc[q * 2], acc[q * 2 + 1]);
    if (active) {
#pragma unroll
        for (int o = 0; o < 32; o++) {
            acc[o] += Xc[((size_t)(b * 32 + o) * Tin + t + dd) * NNODE + n];
            Xn[((size_t)(b * 32 + o) * Tout + t) * NNODE + n] = acc[o];
        }
    }
    int lane = tid & 31, warp = tid >> 5;
#pragma unroll
    for (int o = 0; o < 32; o++) {
        float s = active ? acc[o] : 0.f;
        float q = s * s;
#pragma unroll
        for (int off = 16; off; off >>= 1) {
            s += __shfl_down_sync(0xffffffffu, s, off);
            q += __shfl_down_sync(0xffffffffu, q, off);
        }
        if (lane == 0) { sredS[warp][o] = s; sredQ[warp][o] = q; }
    }
    __syncthreads();
    if (tid < 64) {
        int o = tid & 31;
        bool isq = (tid >= 32);
        float v = 0.f;
#pragma unroll
        for (int w = 0; w < 4; w++) v += (isq ? sredQ[w][o] : sredS[w][o]);
        size_t bidx = (size_t)(blockIdx.z * gridDim.y + blockIdx.y) * gridDim.x + blockIdx.x;
        part[bidx * 64 + tid] = v;
    }
}

// reduce partials -> fused BN scale/shift
__global__ void k_redstats(const float* __restrict__ part, int nblk, float cnt,
                           const float* __restrict__ g, const float* __restrict__ bta,
                           float* __restrict__ ab) {
    int c = blockIdx.x;
    int tid = threadIdx.x;
    double s = 0.0, q = 0.0;
    for (int i = tid; i < nblk; i += 256) {
        s += (double)part[(size_t)i * 64 + c];
        q += (double)part[(size_t)i * 64 + 32 + c];
    }
    __shared__ double rs[256], rq[256];
    rs[tid] = s; rq[tid] = q;
    __syncthreads();
    for (int st = 128; st > 0; st >>= 1) {
        if (tid < st) { rs[tid] += rs[tid + st]; rq[tid] += rq[tid + st]; }
        __syncthreads();
    }
    if (tid == 0) {
        float mean = (float)(rs[0] / cnt);
        float var = (float)(rq[0] / cnt) - mean * mean;
        float a = g[c] * rsqrtf(var + BN_EPS);
        ab[c] = a;
        ab[32 + c] = bta[c] - mean * a;
    }
}

__global__ void k_bnnorm(float* __restrict__ X, const float* __restrict__ ab, int Tout) {
    int idx = blockIdx.x * 256 + threadIdx.x;
    int total = BB * 32 * Tout * NNODE;
    if (idx >= total) return;
    int c = (idx / (Tout * NNODE)) % 32;
    X[idx] = X[idx] * ab[c] + ab[32 + c];
}

// ---------------- output head ----------------
__global__ void k_transpose_skip(const float* __restrict__ skip, float* __restrict__ Srelu) {
    __shared__ float tile[32][33];
    int b = blockIdx.z;
    int n0 = blockIdx.x * 32, c0 = blockIdx.y * 32;
    int n = n0 + threadIdx.x, c = c0 + threadIdx.y;
    tile[threadIdx.y][threadIdx.x] = (n < NNODE) ? skip[(size_t)(b * NSKIPC + c) * NNODE + n] : 0.f;
    __syncthreads();
    int n2 = n0 + threadIdx.y, c2 = c0 + threadIdx.x;
    if (n2 < NNODE)
        Srelu[(size_t)(b * NNODE + n2) * NSKIPC + c2] = fmaxf(tile[threadIdx.x][threadIdx.y], 0.f);
}

__global__ void k_transpose_o1w(const float* __restrict__ o1w, float* __restrict__ o1wT) {
    int idx = blockIdx.x * 256 + threadIdx.x;
    if (idx >= NENDC * NSKIPC) return;
    int h = idx / NSKIPC, c = idx % NSKIPC;
    o1wT[c * NENDC + h] = o1w[idx];
}

__global__ void k_headfinal(const float* __restrict__ H, const float* __restrict__ o1b,
                            const float* __restrict__ o2w, const float* __restrict__ o2b,
                            float* __restrict__ out) {
    int warp = threadIdx.x >> 5, lane = threadIdx.x & 31;
    int row = blockIdx.x * 4 + warp;
    if (row >= BB * NNODE) return;
    int b = row / NNODE, n = row % NNODE;
    const float* Hr = H + (size_t)row * NENDC;
    float h[16];
#pragma unroll
    for (int i = 0; i < 16; i++)
        h[i] = fmaxf(Hr[lane + i * 32] + o1b[lane + i * 32], 0.f);
#pragma unroll
    for (int p = 0; p < NPREDC; p++) {
        float acc = 0.f;
#pragma unroll
        for (int i = 0; i < 16; i++) acc += o2w[p * NENDC + lane + i * 32] * h[i];
#pragma unroll
        for (int off = 16; off; off >>= 1) acc += __shfl_down_sync(0xffffffffu, acc, off);
        if (lane == 0) out[(size_t)(b * NPREDC + p) * NNODE + n] = acc + o2b[p];
    }
}

// ---------------- host launcher ----------------
extern "C" void kernel_launch(void* const* d_in, const int* in_sizes, int n_in,
                              void* d_out, int out_size) {
    const float* inputs = (const float*)d_in[0];
    const float* factor = (const float*)d_in[1];
    const float* map_w  = (const float*)d_in[2];
    const float* map_b  = (const float*)d_in[3];
    const float* a1w    = (const float*)d_in[4];
    const float* a1b    = (const float*)d_in[5];
    const float* a2w    = (const float*)d_in[6];
    const float* a2b    = (const float*)d_in[7];
    const float* a3w    = (const float*)d_in[8];
    const float* a3b    = (const float*)d_in[9];
    const float* enter_w = (const float*)d_in[10];
    const float* enter_b = (const float*)d_in[11];
    const float* filt_w = (const float*)d_in[12];
    const float* filt_b = (const float*)d_in[13];
    const float* gate_w = (const float*)d_in[14];
    const float* gate_b = (const float*)d_in[15];
    const float* skp_w  = (const float*)d_in[16];
    const float* skp_b  = (const float*)d_in[17];
    const float* gc_w   = (const float*)d_in[18];
    const float* gc_b   = (const float*)d_in[19];
    const float* bn_g   = (const float*)d_in[20];
    const float* bn_b   = (const float*)d_in[21];
    const float* o1w    = (const float*)d_in[22];
    const float* o1b    = (const float*)d_in[23];
    const float* o2w    = (const float*)d_in[24];
    const float* o2b    = (const float*)d_in[25];

    float *pScat, *pY, *pX0, *pX1, *pXG, *pSkip, *pSrelu, *pO1T, *pPart, *pAB;
    cudaGetSymbolAddress((void**)&pScat, g_Scat);
    cudaGetSymbolAddress((void**)&pY, g_Y);
    cudaGetSymbolAddress((void**)&pX0, g_X0);
    cudaGetSymbolAddress((void**)&pX1, g_X1);
    cudaGetSymbolAddress((void**)&pXG, g_XG);
    cudaGetSymbolAddress((void**)&pSkip, g_skip);
    cudaGetSymbolAddress((void**)&pSrelu, g_Srelu);
    cudaGetSymbolAddress((void**)&pO1T, g_o1wT);
    cudaGetSymbolAddress((void**)&pPart, g_part);
    cudaGetSymbolAddress((void**)&pAB, g_bnab);

    float* out = (float*)d_out;
    const int ySize = BB * NPREDC * NNODE;
    const int supSize = 2 * NNODE * NNODE;
    int writeSup = (out_size >= ySize + supSize) ? 1 : 0;
    float* outSup = out + ySize;

    // adaptive adjacency (launches 1..3)
    k_pq<<<NNODE, 64>>>(factor, map_w, map_b, a1w, a1b);
    k_adjmlp<<<NNODE, 128>>>(a2w, a2b, a3w, a3b);
    k_softmax<<<2 * NNODE, 256>>>(outSup, writeSup);
    // launch 4: tensor-core GEMM for A^2 (captured by ncu)
    tgemm<<<dim3(4, 4, 2), 256>>>(pScat, pScat, pScat + 500, 500, 500, 500, 2000, 2000, 2000,
                                  1000, 1000, 1000);
    // input split + enter conv
    k_tmp<<<dim3(TT, BB), 64>>>(inputs, factor);
    k_enter<<<dim3(4, RFh, BB), 128>>>(inputs, factor, enter_w, enter_b, pX0);

    static const int Tin[LL] = {13, 12, 10, 9, 7, 6, 4, 3};
    static const int Dd[LL]  = {1, 2, 1, 2, 1, 2, 1, 2};
    static const int To[LL]  = {12, 10, 9, 7, 6, 4, 3, 1};
    float* Xc = pX0;
    float* Xn = pX1;
    for (int i = 0; i < LL; i++) {
        k_gatefilter<<<dim3(4, To[i], BB), 128>>>(Xc, pXG,
            filt_w + i * 2048, filt_b + i * 32, gate_w + i * 2048, gate_b + i * 32,
            Tin[i], To[i], Dd[i]);
        k_skip<<<dim3(63, BB), 256>>>(pXG, pSkip, skp_w + i * 8192, skp_b + i * 256,
                                      To[i], (i == 0) ? 1 : 0);
        if (i < LL - 1) {   // layer 8's graph_conv/BN output is dead code
            int M = BB * 32 * To[i];
            tgemm<<<dim3(16, M / 128), 256>>>(pXG, pScat, pY, M, 2000, 500,
                                              500, 2000, 2000, 0, 0, 0);
            int nblk = 4 * To[i] * BB;
            k_gcres<<<dim3(4, To[i], BB), 128>>>(pXG, pY, Xc, Xn,
                gc_w + i * 5120, gc_b + i * 32, pPart, Tin[i], To[i], Dd[i]);
            k_redstats<<<32, 256>>>(pPart, nblk, (float)(BB * To[i] * NNODE),
                                    bn_g + i * 32, bn_b + i * 32, pAB);
            int tot = BB * 32 * To[i] * NNODE;
            k_bnnorm<<<(tot + 255) / 256, 256>>>(Xn, pAB, To[i]);
            float* t = Xc; Xc = Xn; Xn = t;
        }
    }
    // output head
    k_transpose_skip<<<dim3(16, 8, BB), dim3(32, 32)>>>(pSkip, pSrelu);
    k_transpose_o1w<<<(NENDC * NSKIPC + 255) / 256, 256>>>(o1w, pO1T);
    tgemm<<<dim3(4, 125), 256>>>(pSrelu, pO1T, pY, BB * NNODE, NENDC, NSKIPC,
                                 NSKIPC, NENDC, NENDC, 0, 0, 0);
    k_headfinal<<<(BB * NNODE + 3) / 4, 128>>>(pY, o1b, o2w, o2b, out);
}

// round 5
// speedup vs baseline: 2.0859x; 1.1877x over previous
#include <cuda_runtime.h>
#include <math.h>
#include <stdint.h>

// ---------------- static problem config ----------------
#define BB 32
#define TT 12
#define NNODE 500
#define NSKIPC 256
#define NENDC 512
#define NPREDC 12
#define LL 8
#define RFh 13
#define BN_EPS 1e-5f

typedef unsigned long long ull;
typedef unsigned int u32;

__device__ __forceinline__ ull pack2(float lo, float hi) {
    ull r; asm("mov.b64 %0,{%1,%2};" : "=l"(r) : "f"(lo), "f"(hi)); return r;
}
__device__ __forceinline__ ull fma2(ull a, ull b, ull c) {
    ull d; asm("fma.rn.f32x2 %0,%1,%2,%3;" : "=l"(d) : "l"(a), "l"(b), "l"(c)); return d;
}
__device__ __forceinline__ void unpack2(ull v, float& lo, float& hi) {
    asm("mov.b64 {%0,%1},%2;" : "=f"(lo), "=f"(hi) : "l"(v));
}
__device__ __forceinline__ float to_tf32(float x) {
    u32 r; asm("cvt.rna.tf32.f32 %0, %1;" : "=r"(r) : "f"(x));
    return __uint_as_float(r);
}
__device__ __forceinline__ void mma_tf32(float* c, const u32* a, const u32* b) {
    asm("mma.sync.aligned.m16n8k8.row.col.f32.tf32.tf32.f32 "
        "{%0,%1,%2,%3},{%4,%5,%6,%7},{%8,%9},{%0,%1,%2,%3};"
        : "+f"(c[0]), "+f"(c[1]), "+f"(c[2]), "+f"(c[3])
        : "r"(a[0]), "r"(a[1]), "r"(a[2]), "r"(a[3]), "r"(b[0]), "r"(b[1]));
}

// ---------------- device scratch ----------------
__device__ float g_P[NNODE * 64];
__device__ float g_Q[NNODE * 64];
__device__ float g_eraw[2 * NNODE * NNODE];
__device__ float g_Scat[NNODE * 2000];            // [v][ A0 | A0^2 | A1 | A1^2 ]
__device__ float g_tmp[BB * TT * 32 * 2];
__device__ float g_X0[BB * 32 * RFh * NNODE];
__device__ float g_X1[BB * 32 * RFh * NNODE];
__device__ float g_XG[BB * 32 * 12 * NNODE];
__device__ float g_Y[12288 * 2000];               // diffusion outputs; reused as head hidden H
__device__ float g_XGcat[BB * 256 * NNODE];       // last-t gated slices, rows (l*32+c)
__device__ float g_Wcat[256 * 256];               // skip weights re-laid [o][l*32+c]
__device__ float g_skip[BB * NSKIPC * NNODE];
__device__ float g_Srelu[BB * NNODE * NSKIPC];
__device__ float g_o1wT[NSKIPC * NENDC];
__device__ float g_part[1536 * 64];               // per-block BN partial sums
__device__ float g_bnab[(LL + 1) * 64];           // per-layer fused BN scale/shift; slot LL = identity

// ---------------- small init kernels ----------------
__global__ void k_initab() {
    int t = threadIdx.x;
    if (t < 64) g_bnab[LL * 64 + t] = (t < 32) ? 1.f : 0.f;
}

__global__ void k_wcat(const float* __restrict__ skp_w) {
    int idx = blockIdx.x * 256 + threadIdx.x;
    if (idx >= 256 * 256) return;
    int o = idx >> 8, r = idx & 255;
    int l = r >> 5, c = r & 31;
    g_Wcat[idx] = skp_w[l * 8192 + o * 32 + c];
}

// ---------------- adjacency ----------------
__global__ void k_pq(const float* __restrict__ factor, const float* __restrict__ map_w,
                     const float* __restrict__ map_b,
                     const float* __restrict__ a1w, const float* __restrict__ a1b) {
    __shared__ float vv[32];
    int j = blockIdx.x, h = threadIdx.x;   // 64 threads
    if (h < 32) {
        float acc = map_b[h];
#pragma unroll
        for (int u = 0; u < 32; u++) acc += factor[j * 32 + u] * map_w[u * 32 + h];
        vv[h] = fmaxf(acc, 0.f);
    }
    __syncthreads();
    float p = 0.f, q = a1b[h];
#pragma unroll
    for (int d = 0; d < 32; d++) {
        p += vv[d] * a1w[d * 64 + h];
        q += vv[d] * a1w[(32 + d) * 64 + h];
    }
    g_P[j * 64 + h] = p;
    g_Q[j * 64 + h] = q;
}

__global__ void k_adjmlp(const float* __restrict__ a2w, const float* __restrict__ a2b,
                         const float* __restrict__ a3w, const float* __restrict__ a3b) {
    __shared__ float Pt[128][65];
    __shared__ __align__(16) float sA2[64][32];
    __shared__ float sQ[64];
    __shared__ float sA3[64];
    __shared__ float sA2b[32];
    __shared__ float sA3b[2];
    int i = blockIdx.x, tid = threadIdx.x;
    for (int k = tid; k < 64 * 32; k += 128) sA2[k / 32][k % 32] = a2w[k];
    if (tid < 64) { sQ[tid] = g_Q[i * 64 + tid]; sA3[tid] = a3w[tid]; }
    if (tid < 32) sA2b[tid] = a2b[tid];
    if (tid < 2) sA3b[tid] = a3b[tid];
    for (int j0 = 0; j0 < NNODE; j0 += 128) {
        __syncthreads();
        int cnt = min(128, NNODE - j0);
        for (int k = tid; k < cnt * 64; k += 128)
            Pt[k / 64][k % 64] = g_P[(j0 + (k / 64)) * 64 + (k % 64)];
        __syncthreads();
        if (tid < cnt) {
            int j = j0 + tid;
            float h1[64];
#pragma unroll
            for (int h = 0; h < 64; h++) h1[h] = fmaxf(Pt[tid][h] + sQ[h], 0.f);
            float e0 = sA3b[0], e1 = sA3b[1];
#pragma unroll
            for (int c = 0; c < 32; c++) {
                float acc = sA2b[c];
#pragma unroll
                for (int h = 0; h < 64; h++) acc += h1[h] * sA2[h][c];
                acc = fmaxf(acc, 0.f);
                e0 += acc * sA3[c * 2];
                e1 += acc * sA3[c * 2 + 1];
            }
            g_eraw[i * NNODE + j] = e0;
            g_eraw[NNODE * NNODE + i * NNODE + j] = e1;
        }
    }
}

__global__ void k_softmax(float* __restrict__ outSup, int writeSup) {
    int bid = blockIdx.x;
    int e = bid / NNODE, i = bid % NNODE;
    const float* row = g_eraw + e * NNODE * NNODE + i * NNODE;
    __shared__ float red[256];
    int tid = threadIdx.x;
    float m = -1e30f;
    for (int j = tid; j < NNODE; j += 256) m = fmaxf(m, row[j]);
    red[tid] = m; __syncthreads();
    for (int s = 128; s > 0; s >>= 1) { if (tid < s) red[tid] = fmaxf(red[tid], red[tid + s]); __syncthreads(); }
    m = red[0]; __syncthreads();
    float sum = 0.f;
    for (int j = tid; j < NNODE; j += 256) sum += expf(row[j] - m);
    red[tid] = sum; __syncthreads();
    for (int s = 128; s > 0; s >>= 1) { if (tid < s) red[tid] += red[tid + s]; __syncthreads(); }
    float inv = 1.f / red[0];
    for (int j = tid; j < NNODE; j += 256) {
        float p = expf(row[j] - m) * inv;
        if (j == i) p = fmaxf(p, 1.f);
        g_Scat[i * 2000 + e * 1000 + j] = p;
        if (writeSup) outSup[(e * NNODE + i) * NNODE + j] = p;
    }
}

// ---------------- tf32 tensor-core GEMM: 128x128 tile, KC=16, double-buffered ----------------
__global__ __launch_bounds__(256)
void tgemm(const float* __restrict__ A, const float* __restrict__ B, float* __restrict__ C,
           int M, int N, int K, int lda, int ldb, int ldc,
           int sA, int sB, int sC) {
    __shared__ __align__(16) float As[2][16][136];
    __shared__ __align__(16) float Bs[2][16][136];
    A += (size_t)blockIdx.z * sA;
    B += (size_t)blockIdx.z * sB;
    C += (size_t)blockIdx.z * sC;
    int tid = threadIdx.x;
    int m0 = blockIdx.y * 128, n0 = blockIdx.x * 128;
    int lane = tid & 31, wid = tid >> 5;
    int wm = wid & 1, wn = wid >> 1;
    int gid = lane >> 2, tig = lane & 3;
    int lm = tid >> 1, lrh = tid & 1;
    int lkl = tid >> 4, lnq = (tid & 15) << 3;

    float acc[4][4][4];
#pragma unroll
    for (int mi = 0; mi < 4; mi++)
#pragma unroll
        for (int ni = 0; ni < 4; ni++)
#pragma unroll
            for (int r = 0; r < 4; r++) acc[mi][ni][r] = 0.f;

    int nkt = (K + 15) / 16;
    {
        float av[8];
        int row = m0 + lm, c0 = lrh * 8;
        if (row < M && c0 + 7 < K) {
            float4 p = *(const float4*)(A + (size_t)row * lda + c0);
            float4 q = *(const float4*)(A + (size_t)row * lda + c0 + 4);
            av[0]=p.x; av[1]=p.y; av[2]=p.z; av[3]=p.w; av[4]=q.x; av[5]=q.y; av[6]=q.z; av[7]=q.w;
        } else {
#pragma unroll
            for (int l = 0; l < 8; l++)
                av[l] = (row < M && c0 + l < K) ? A[(size_t)row * lda + c0 + l] : 0.f;
        }
#pragma unroll
        for (int l = 0; l < 8; l++) As[0][lrh * 8 + l][lm] = to_tf32(av[l]);
        float bv[8];
        int br = lkl, bc = n0 + lnq;
        if (br < K && bc + 7 < N) {
            float4 p = *(const float4*)(B + (size_t)br * ldb + bc);
            float4 q = *(const float4*)(B + (size_t)br * ldb + bc + 4);
            bv[0]=p.x; bv[1]=p.y; bv[2]=p.z; bv[3]=p.w; bv[4]=q.x; bv[5]=q.y; bv[6]=q.z; bv[7]=q.w;
        } else {
#pragma unroll
            for (int l = 0; l < 8; l++)
                bv[l] = (br < K && bc + l < N) ? B[(size_t)br * ldb + bc + l] : 0.f;
        }
        float4 f0 = make_float4(to_tf32(bv[0]), to_tf32(bv[1]), to_tf32(bv[2]), to_tf32(bv[3]));
        float4 f1 = make_float4(to_tf32(bv[4]), to_tf32(bv[5]), to_tf32(bv[6]), to_tf32(bv[7]));
        *(float4*)&Bs[0][lkl][lnq] = f0;
        *(float4*)&Bs[0][lkl][lnq + 4] = f1;
    }
    __syncthreads();

    for (int kt = 0; kt < nkt; kt++) {
        int cur = kt & 1;
        bool hn = (kt + 1 < nkt);
        float av[8], bv[8];
        if (hn) {
            int kc0 = (kt + 1) * 16;
            int row = m0 + lm, c0 = kc0 + lrh * 8;
            if (row < M && c0 + 7 < K) {
                float4 p = *(const float4*)(A + (size_t)row * lda + c0);
                float4 q = *(const float4*)(A + (size_t)row * lda + c0 + 4);
                av[0]=p.x; av[1]=p.y; av[2]=p.z; av[3]=p.w; av[4]=q.x; av[5]=q.y; av[6]=q.z; av[7]=q.w;
            } else {
#pragma unroll
                for (int l = 0; l < 8; l++)
                    av[l] = (row < M && c0 + l < K) ? A[(size_t)row * lda + c0 + l] : 0.f;
            }
            int br = kc0 + lkl, bc = n0 + lnq;
            if (br < K && bc + 7 < N) {
                float4 p = *(const float4*)(B + (size_t)br * ldb + bc);
                float4 q = *(const float4*)(B + (size_t)br * ldb + bc + 4);
                bv[0]=p.x; bv[1]=p.y; bv[2]=p.z; bv[3]=p.w; bv[4]=q.x; bv[5]=q.y; bv[6]=q.z; bv[7]=q.w;
            } else {
#pragma unroll
                for (int l = 0; l < 8; l++)
                    bv[l] = (br < K && bc + l < N) ? B[(size_t)br * ldb + bc + l] : 0.f;
            }
        }
#pragma unroll
        for (int ks = 0; ks < 16; ks += 8) {
            u32 af[4][4];
            u32 bf[4][2];
#pragma unroll
            for (int mi = 0; mi < 4; mi++) {
                int mb = wm * 64 + mi * 16 + gid;
                af[mi][0] = __float_as_uint(As[cur][ks + tig][mb]);
                af[mi][1] = __float_as_uint(As[cur][ks + tig][mb + 8]);
                af[mi][2] = __float_as_uint(As[cur][ks + tig + 4][mb]);
                af[mi][3] = __float_as_uint(As[cur][ks + tig + 4][mb + 8]);
            }
#pragma unroll
            for (int ni = 0; ni < 4; ni++) {
                int nb = wn * 32 + ni * 8 + gid;
                bf[ni][0] = __float_as_uint(Bs[cur][ks + tig][nb]);
                bf[ni][1] = __float_as_uint(Bs[cur][ks + tig + 4][nb]);
            }
#pragma unroll
            for (int mi = 0; mi < 4; mi++)
#pragma unroll
                for (int ni = 0; ni < 4; ni++)
                    mma_tf32(acc[mi][ni], af[mi], bf[ni]);
        }
        if (hn) {
            int nxt = cur ^ 1;
#pragma unroll
            for (int l = 0; l < 8; l++) As[nxt][lrh * 8 + l][lm] = to_tf32(av[l]);
            float4 f0 = make_float4(to_tf32(bv[0]), to_tf32(bv[1]), to_tf32(bv[2]), to_tf32(bv[3]));
            float4 f1 = make_float4(to_tf32(bv[4]), to_tf32(bv[5]), to_tf32(bv[6]), to_tf32(bv[7]));
            *(float4*)&Bs[nxt][lkl][lnq] = f0;
            *(float4*)&Bs[nxt][lkl][lnq + 4] = f1;
            __syncthreads();
        }
    }
#pragma unroll
    for (int mi = 0; mi < 4; mi++) {
        int r0 = m0 + wm * 64 + mi * 16 + gid;
        int r1 = r0 + 8;
#pragma unroll
        for (int ni = 0; ni < 4; ni++) {
            int cc = n0 + wn * 32 + ni * 8 + tig * 2;
            if (r0 < M) {
                if (cc + 1 < N) *(float2*)(C + (size_t)r0 * ldc + cc) = make_float2(acc[mi][ni][0], acc[mi][ni][1]);
                else if (cc < N) C[(size_t)r0 * ldc + cc] = acc[mi][ni][0];
            }
            if (r1 < M) {
                if (cc + 1 < N) *(float2*)(C + (size_t)r1 * ldc + cc) = make_float2(acc[mi][ni][2], acc[mi][ni][3]);
                else if (cc < N) C[(size_t)r1 * ldc + cc] = acc[mi][ni][2];
            }
        }
    }
}

// ---------------- input split + enter ----------------
// 256 threads: output (u,f) = tid/4, r = tid%4 reduces n strided by 4, then shfl.
__global__ void k_tmp(const float* __restrict__ inputs, const float* __restrict__ factor) {
    int t = blockIdx.x, b = blockIdx.y, tid = threadIdx.x;
    int o = tid >> 2, r = tid & 3;       // o in [0,64)
    int u = o >> 1, f = o & 1;
    const float* inp = inputs + ((size_t)(b * TT + t) * NNODE) * 2 + f;
    float acc = 0.f;
    for (int n = r; n < NNODE; n += 4) acc += inp[n * 2] * factor[n * 32 + u];
    acc += __shfl_down_sync(0xffffffffu, acc, 2);
    acc += __shfl_down_sync(0xffffffffu, acc, 1);
    if (r == 0) g_tmp[(b * TT + t) * 64 + o] = acc;
}

__global__ void k_enter(const float* __restrict__ inputs, const float* __restrict__ factor,
                        const float* __restrict__ ew, const float* __restrict__ eb,
                        float* __restrict__ X0) {
    __shared__ float sw[128], sb[32], stmp[64];
    int b = blockIdx.z, tp = blockIdx.y;
    int tid = threadIdx.x;
    if (tid < 128) sw[tid] = ew[tid];
    if (tid < 32) sb[tid] = eb[tid];
    if (tp > 0 && tid < 64) stmp[tid] = g_tmp[(b * TT + (tp - 1)) * 64 + tid];
    __syncthreads();
    int n = blockIdx.x * 128 + tid;
    if (n >= NNODE) return;
    if (tp == 0) {
#pragma unroll
        for (int o = 0; o < 32; o++)
            X0[((size_t)(b * 32 + o) * RFh + 0) * NNODE + n] = sb[o];
    } else {
        int t = tp - 1;
        float s0 = 0.f, s1 = 0.f;
#pragma unroll
        for (int u = 0; u < 32; u++) {
            float fv = factor[n * 32 + u];
            s0 += fv * stmp[u * 2];
            s1 += fv * stmp[u * 2 + 1];
        }
        float i0 = inputs[((size_t)(b * TT + t) * NNODE + n) * 2 + 0];
        float i1 = inputs[((size_t)(b * TT + t) * NNODE + n) * 2 + 1];
        float r0 = i0 - s0, r1 = i1 - s1;
#pragma unroll
        for (int o = 0; o < 32; o++) {
            float v = sb[o] + sw[o * 4] * s0 + sw[o * 4 + 1] * s1 + sw[o * 4 + 2] * r0 + sw[o * 4 + 3] * r1;
            X0[((size_t)(b * 32 + o) * RFh + tp) * NNODE + n] = v;
        }
    }
}

// ---------------- gated dilated temporal conv; BN affine fused on input ----------------
// smem weight layout [c][kk][o]; LDS.128 pairs. Writes last-t slice into XGcat.
__global__ void k_gatefilter(const float* __restrict__ X, float* __restrict__ XG,
                             float* __restrict__ XGcat,
                             const float* __restrict__ fw, const float* __restrict__ fb,
                             const float* __restrict__ gw, const float* __restrict__ gb,
                             const float* __restrict__ abPrev,
                             int Tin, int Tout, int dd, int layer) {
    __shared__ __align__(16) float swf[2048];
    __shared__ __align__(16) float swg[2048];
    __shared__ float sfb[32], sgb[32], sA[32], sB[32];
    int tid = threadIdx.x;
    for (int idx = tid; idx < 2048; idx += 128) {
        int c = idx >> 6, r = idx & 63, kk = r >> 5, o = r & 31;
        swf[idx] = fw[(o << 6) + (c << 1) + kk];
        swg[idx] = gw[(o << 6) + (c << 1) + kk];
    }
    if (tid < 32) {
        sfb[tid] = fb[tid]; sgb[tid] = gb[tid];
        sA[tid] = abPrev[tid]; sB[tid] = abPrev[32 + tid];
    }
    __syncthreads();
    int n = blockIdx.x * 128 + tid;
    if (n >= NNODE) return;
    int t = blockIdx.y, b = blockIdx.z;
    ull fa2[16], ga2[16];
#pragma unroll
    for (int p = 0; p < 16; p++) {
        fa2[p] = pack2(sfb[p * 2], sfb[p * 2 + 1]);
        ga2[p] = pack2(sgb[p * 2], sgb[p * 2 + 1]);
    }
    const float* Xb = X + (size_t)(b * 32) * Tin * NNODE + n;
    for (int c = 0; c < 32; c++) {
        float xa = Xb[(size_t)(c * Tin + t) * NNODE] * sA[c] + sB[c];
        float xb = Xb[(size_t)(c * Tin + t + dd) * NNODE] * sA[c] + sB[c];
        ull xad = pack2(xa, xa), xbd = pack2(xb, xb);
        const ulonglong2* wf0 = (const ulonglong2*)&swf[c * 64];
        const ulonglong2* wf1 = (const ulonglong2*)&swf[c * 64 + 32];
        const ulonglong2* wg0 = (const ulonglong2*)&swg[c * 64];
        const ulonglong2* wg1 = (const ulonglong2*)&swg[c * 64 + 32];
#pragma unroll
        for (int p = 0; p < 8; p++) {
            ulonglong2 wa = wf0[p];
            fa2[p * 2 + 0] = fma2(xad, wa.x, fa2[p * 2 + 0]);
            fa2[p * 2 + 1] = fma2(xad, wa.y, fa2[p * 2 + 1]);
            ulonglong2 wb = wf1[p];
            fa2[p * 2 + 0] = fma2(xbd, wb.x, fa2[p * 2 + 0]);
            fa2[p * 2 + 1] = fma2(xbd, wb.y, fa2[p * 2 + 1]);
            ulonglong2 wc = wg0[p];
            ga2[p * 2 + 0] = fma2(xad, wc.x, ga2[p * 2 + 0]);
            ga2[p * 2 + 1] = fma2(xad, wc.y, ga2[p * 2 + 1]);
            ulonglong2 wd = wg1[p];
            ga2[p * 2 + 0] = fma2(xbd, wd.x, ga2[p * 2 + 0]);
            ga2[p * 2 + 1] = fma2(xbd, wd.y, ga2[p * 2 + 1]);
        }
    }
    bool last = (t == Tout - 1);
#pragma unroll
    for (int p = 0; p < 16; p++) {
        float f0, f1, g0, g1;
        unpack2(fa2[p], f0, f1);
        unpack2(ga2[p], g0, g1);
        float s0 = 1.f / (1.f + expf(-g0));
        float s1 = 1.f / (1.f + expf(-g1));
        float v0 = tanhf(f0) * s0, v1 = tanhf(f1) * s1;
        XG[((size_t)(b * 32 + p * 2 + 0) * Tout + t) * NNODE + n] = v0;
        XG[((size_t)(b * 32 + p * 2 + 1) * Tout + t) * NNODE + n] = v1;
        if (last) {
            XGcat[((size_t)b * 256 + layer * 32 + p * 2 + 0) * NNODE + n] = v0;
            XGcat[((size_t)b * 256 + layer * 32 + p * 2 + 1) * NNODE + n] = v1;
        }
    }
}

// ---------------- gc 1x1 + residual(BN-fused) + BN partial stats; 2 nodes/thread ----------------
__global__ void k_gcres(const float* __restrict__ XG, const float* __restrict__ Y,
                        const float* __restrict__ Xc, float* __restrict__ Xn,
                        const float* __restrict__ gcw, const float* __restrict__ gcb,
                        const float* __restrict__ abPrev,
                        float* __restrict__ part, int Tin, int Tout, int dd) {
    __shared__ __align__(16) float swg[160 * 32];
    __shared__ float sgb[32], sA[32], sB[32];
    __shared__ float sredS[4][32];
    __shared__ float sredQ[4][32];
    int tid = threadIdx.x;
    for (int idx = tid; idx < 160 * 32; idx += 128) {
        int c = idx / 32, o = idx % 32;
        swg[idx] = gcw[o * 160 + c];
    }
    if (tid < 32) { sgb[tid] = gcb[tid]; sA[tid] = abPrev[tid]; sB[tid] = abPrev[32 + tid]; }
    __syncthreads();
    int n0 = blockIdx.x * 256 + tid;
    int n1 = n0 + 128;
    int t = blockIdx.y, b = blockIdx.z;
    bool a0 = (n0 < NNODE), a1 = (n1 < NNODE);
    ull acc0[16], acc1[16];
#pragma unroll
    for (int q = 0; q < 16; q++) {
        ull bias = pack2(sgb[q * 2], sgb[q * 2 + 1]);
        acc0[q] = a0 ? bias : pack2(0.f, 0.f);
        acc1[q] = a1 ? bias : pack2(0.f, 0.f);
    }
    for (int c = 0; c < 32; c++) {
        size_t base = ((size_t)(b * 32 + c) * Tout + t) * NNODE;
        float v0 = a0 ? XG[base + n0] : 0.f;
        float v1 = a1 ? XG[base + n1] : 0.f;
        ull vd0 = pack2(v0, v0), vd1 = pack2(v1, v1);
        const ulonglong2* w2 = (const ulonglong2*)&swg[c * 32];
#pragma unroll
        for (int q = 0; q < 8; q++) {
            ulonglong2 w = w2[q];
            acc0[q * 2 + 0] = fma2(vd0, w.x, acc0[q * 2 + 0]);
            acc0[q * 2 + 1] = fma2(vd0, w.y, acc0[q * 2 + 1]);
            acc1[q * 2 + 0] = fma2(vd1, w.x, acc1[q * 2 + 0]);
            acc1[q * 2 + 1] = fma2(vd1, w.y, acc1[q * 2 + 1]);
        }
    }
    for (int e = 0; e < 4; e++) {
        for (int c = 0; c < 32; c++) {
            size_t m = ((size_t)(b * 32 + c) * Tout + t) * 2000 + e * 500;
            float v0 = a0 ? Y[m + n0] : 0.f;
            float v1 = a1 ? Y[m + n1] : 0.f;
            ull vd0 = pack2(v0, v0), vd1 = pack2(v1, v1);
            const ulonglong2* w2 = (const ulonglong2*)&swg[(32 + e * 32 + c) * 32];
#pragma unroll
            for (int q = 0; q < 8; q++) {
                ulonglong2 w = w2[q];
                acc0[q * 2 + 0] = fma2(vd0, w.x, acc0[q * 2 + 0]);
                acc0[q * 2 + 1] = fma2(vd0, w.y, acc0[q * 2 + 1]);
                acc1[q * 2 + 0] = fma2(vd1, w.x, acc1[q * 2 + 0]);
                acc1[q * 2 + 1] = fma2(vd1, w.y, acc1[q * 2 + 1]);
            }
        }
    }
    float f0[32], f1[32];
#pragma unroll
    for (int q = 0; q < 16; q++) {
        unpack2(acc0[q], f0[q * 2], f0[q * 2 + 1]);
        unpack2(acc1[q], f1[q * 2], f1[q * 2 + 1]);
    }
#pragma unroll
    for (int o = 0; o < 32; o++) {
        size_t rbase = ((size_t)(b * 32 + o) * Tin + t + dd) * NNODE;
        size_t wbase = ((size_t)(b * 32 + o) * Tout + t) * NNODE;
        if (a0) {
            f0[o] += Xc[rbase + n0] * sA[o] + sB[o];
            Xn[wbase + n0] = f0[o];
        }
        if (a1) {
            f1[o] += Xc[rbase + n1] * sA[o] + sB[o];
            Xn[wbase + n1] = f1[o];
        }
    }
    int lane = tid & 31, warp = tid >> 5;
#pragma unroll
    for (int o = 0; o < 32; o++) {
        float s = (a0 ? f0[o] : 0.f) + (a1 ? f1[o] : 0.f);
        float q = (a0 ? f0[o] * f0[o] : 0.f) + (a1 ? f1[o] * f1[o] : 0.f);
#pragma unroll
        for (int off = 16; off; off >>= 1) {
            s += __shfl_down_sync(0xffffffffu, s, off);
            q += __shfl_down_sync(0xffffffffu, q, off);
        }
        if (lane == 0) { sredS[warp][o] = s; sredQ[warp][o] = q; }
    }
    __syncthreads();
    if (tid < 64) {
        int o = tid & 31;
        bool isq = (tid >= 32);
        float v = 0.f;
#pragma unroll
        for (int w = 0; w < 4; w++) v += (isq ? sredQ[w][o] : sredS[w][o]);
        size_t bidx = (size_t)(blockIdx.z * gridDim.y + blockIdx.y) * gridDim.x + blockIdx.x;
        part[bidx * 64 + tid] = v;
    }
}

// reduce partials -> fused BN scale/shift into per-layer slot
__global__ void k_redstats(const float* __restrict__ part, int nblk, float cnt,
                           const float* __restrict__ g, const float* __restrict__ bta,
                           float* __restrict__ ab) {
    int c = blockIdx.x;
    int tid = threadIdx.x;
    double s = 0.0, q = 0.0;
    for (int i = tid; i < nblk; i += 256) {
        s += (double)part[(size_t)i * 64 + c];
        q += (double)part[(size_t)i * 64 + 32 + c];
    }
    __shared__ double rs[256], rq[256];
    rs[tid] = s; rq[tid] = q;
    __syncthreads();
    for (int st = 128; st > 0; st >>= 1) {
        if (tid < st) { rs[tid] += rs[tid + st]; rq[tid] += rq[tid + st]; }
        __syncthreads();
    }
    if (tid == 0) {
        float mean = (float)(rs[0] / cnt);
        float var = (float)(rq[0] / cnt) - mean * mean;
        float a = g[c] * rsqrtf(var + BN_EPS);
        ab[c] = a;
        ab[32 + c] = bta[c] - mean * a;
    }
}

// ---------------- output head ----------------
// transpose + relu + add summed skip biases
__global__ void k_transpose_skip(const float* __restrict__ skip, const float* __restrict__ skp_b,
                                 float* __restrict__ Srelu) {
    __shared__ float tile[32][33];
    int b = blockIdx.z;
    int n0 = blockIdx.x * 32, c0 = blockIdx.y * 32;
    int n = n0 + threadIdx.x, c = c0 + threadIdx.y;
    tile[threadIdx.y][threadIdx.x] = (n < NNODE) ? skip[(size_t)(b * NSKIPC + c) * NNODE + n] : 0.f;
    __syncthreads();
    int n2 = n0 + threadIdx.y, c2 = c0 + threadIdx.x;
    float bsum = 0.f;
#pragma unroll
    for (int l = 0; l < LL; l++) bsum += skp_b[l * 256 + c2];
    if (n2 < NNODE)
        Srelu[(size_t)(b * NNODE + n2) * NSKIPC + c2] = fmaxf(tile[threadIdx.x][threadIdx.y] + bsum, 0.f);
}

__global__ void k_transpose_o1w(const float* __restrict__ o1w, float* __restrict__ o1wT) {
    int idx = blockIdx.x * 256 + threadIdx.x;
    if (idx >= NENDC * NSKIPC) return;
    int h = idx / NSKIPC, c = idx % NSKIPC;
    o1wT[c * NENDC + h] = o1w[idx];
}

__global__ void k_headfinal(const float* __restrict__ H, const float* __restrict__ o1b,
                            const float* __restrict__ o2w, const float* __restrict__ o2b,
                            float* __restrict__ out) {
    int warp = threadIdx.x >> 5, lane = threadIdx.x & 31;
    int row = blockIdx.x * 4 + warp;
    if (row >= BB * NNODE) return;
    int b = row / NNODE, n = row % NNODE;
    const float* Hr = H + (size_t)row * NENDC;
    float h[16];
#pragma unroll
    for (int i = 0; i < 16; i++)
        h[i] = fmaxf(Hr[lane + i * 32] + o1b[lane + i * 32], 0.f);
#pragma unroll
    for (int p = 0; p < NPREDC; p++) {
        float acc = 0.f;
#pragma unroll
        for (int i = 0; i < 16; i++) acc += o2w[p * NENDC + lane + i * 32] * h[i];
#pragma unroll
        for (int off = 16; off; off >>= 1) acc += __shfl_down_sync(0xffffffffu, acc, off);
        if (lane == 0) out[(size_t)(b * NPREDC + p) * NNODE + n] = acc + o2b[p];
    }
}

// ---------------- host launcher ----------------
extern "C" void kernel_launch(void* const* d_in, const int* in_sizes, int n_in,
                              void* d_out, int out_size) {
    const float* inputs = (const float*)d_in[0];
    const float* factor = (const float*)d_in[1];
    const float* map_w  = (const float*)d_in[2];
    const float* map_b  = (const float*)d_in[3];
    const float* a1w    = (const float*)d_in[4];
    const float* a1b    = (const float*)d_in[5];
    const float* a2w    = (const float*)d_in[6];
    const float* a2b    = (const float*)d_in[7];
    const float* a3w    = (const float*)d_in[8];
    const float* a3b    = (const float*)d_in[9];
    const float* enter_w = (const float*)d_in[10];
    const float* enter_b = (const float*)d_in[11];
    const float* filt_w = (const float*)d_in[12];
    const float* filt_b = (const float*)d_in[13];
    const float* gate_w = (const float*)d_in[14];
    const float* gate_b = (const float*)d_in[15];
    const float* skp_w  = (const float*)d_in[16];
    const float* skp_b  = (const float*)d_in[17];
    const float* gc_w   = (const float*)d_in[18];
    const float* gc_b   = (const float*)d_in[19];
    const float* bn_g   = (const float*)d_in[20];
    const float* bn_b   = (const float*)d_in[21];
    const float* o1w    = (const float*)d_in[22];
    const float* o1b    = (const float*)d_in[23];
    const float* o2w    = (const float*)d_in[24];
    const float* o2b    = (const float*)d_in[25];

    float *pScat, *pY, *pX0, *pX1, *pXG, *pXGcat, *pWcat, *pSkip, *pSrelu, *pO1T, *pPart, *pAB;
    cudaGetSymbolAddress((void**)&pScat, g_Scat);
    cudaGetSymbolAddress((void**)&pY, g_Y);
    cudaGetSymbolAddress((void**)&pX0, g_X0);
    cudaGetSymbolAddress((void**)&pX1, g_X1);
    cudaGetSymbolAddress((void**)&pXG, g_XG);
    cudaGetSymbolAddress((void**)&pXGcat, g_XGcat);
    cudaGetSymbolAddress((void**)&pWcat, g_Wcat);
    cudaGetSymbolAddress((void**)&pSkip, g_skip);
    cudaGetSymbolAddress((void**)&pSrelu, g_Srelu);
    cudaGetSymbolAddress((void**)&pO1T, g_o1wT);
    cudaGetSymbolAddress((void**)&pPart, g_part);
    cudaGetSymbolAddress((void**)&pAB, g_bnab);

    float* out = (float*)d_out;
    const int ySize = BB * NPREDC * NNODE;
    const int supSize = 2 * NNODE * NNODE;
    int writeSup = (out_size >= ySize + supSize) ? 1 : 0;
    float* outSup = out + ySize;

    static const int Tin[LL] = {13, 12, 10, 9, 7, 6, 4, 3};
    static const int Dd[LL]  = {1, 2, 1, 2, 1, 2, 1, 2};
    static const int To[LL]  = {12, 10, 9, 7, 6, 4, 3, 1};

    // input split + enter + identity-BN slot, then layer-0 gatefilter (4th launch -> ncu capture)
    k_tmp<<<dim3(TT, BB), 256>>>(inputs, factor);
    k_enter<<<dim3(4, RFh, BB), 128>>>(inputs, factor, enter_w, enter_b, pX0);
    k_initab<<<1, 64>>>();
    k_gatefilter<<<dim3(4, To[0], BB), 128>>>(pX0, pXG, pXGcat,
        filt_w, filt_b, gate_w, gate_b, pAB + LL * 64, Tin[0], To[0], Dd[0], 0);
    // adaptive adjacency
    k_pq<<<NNODE, 64>>>(factor, map_w, map_b, a1w, a1b);
    k_adjmlp<<<NNODE, 128>>>(a2w, a2b, a3w, a3b);
    k_softmax<<<2 * NNODE, 256>>>(outSup, writeSup);
    tgemm<<<dim3(4, 4, 2), 256>>>(pScat, pScat, pScat + 500, 500, 500, 500, 2000, 2000, 2000,
                                  1000, 1000, 1000);
    k_wcat<<<256, 256>>>(skp_w);

    float* Xc = pX0;
    float* Xn = pX1;
    for (int i = 0; i < LL - 1; i++) {
        int slotPrev = (i == 0) ? LL : (i - 1);
        int M = BB * 32 * To[i];
        tgemm<<<dim3(16, M / 128), 256>>>(pXG, pScat, pY, M, 2000, 500,
                                          500, 2000, 2000, 0, 0, 0);
        k_gcres<<<dim3(2, To[i], BB), 128>>>(pXG, pY, Xc, Xn,
            gc_w + i * 5120, gc_b + i * 32, pAB + slotPrev * 64, pPart,
            Tin[i], To[i], Dd[i]);
        int nblk = 2 * To[i] * BB;
        k_redstats<<<32, 256>>>(pPart, nblk, (float)(BB * To[i] * NNODE),
                                bn_g + i * 32, bn_b + i * 32, pAB + i * 64);
        // next layer's gated conv (consumes Xn with layer-i BN applied lazily)
        int j = i + 1;
        k_gatefilter<<<dim3(4, To[j], BB), 128>>>(Xn, pXG, pXGcat,
            filt_w + j * 2048, filt_b + j * 32, gate_w + j * 2048, gate_b + j * 32,
            pAB + i * 64, Tin[j], To[j], Dd[j], j);
        float* t = Xc; Xc = Xn; Xn = t;
    }
    // skip = Wcat @ XGcat  (batched over b)
    tgemm<<<dim3(4, 2, BB), 256>>>(pWcat, pXGcat, pSkip, 256, NNODE, 256,
                                   256, NNODE, NNODE, 0, 256 * NNODE, 256 * NNODE);
    // output head
    k_transpose_skip<<<dim3(16, 8, BB), dim3(32, 32)>>>(pSkip, skp_b, pSrelu);
    k_transpose_o1w<<<(NENDC * NSKIPC + 255) / 256, 256>>>(o1w, pO1T);
    tgemm<<<dim3(4, 125), 256>>>(pSrelu, pO1T, pY, BB * NNODE, NENDC, NSKIPC,
                                 NSKIPC, NENDC, NENDC, 0, 0, 0);
    k_headfinal<<<(BB * NNODE + 3) / 4, 128>>>(pY, o1b, o2w, o2b, out);
}